// round 1
// baseline (speedup 1.0000x reference)
#include <cuda_runtime.h>
#include <cuda_bf16.h>
#include <math.h>

#define S_LEN 3072
#define DIM   2048
#define NH    16
#define HD    128

// ---------------- scratch (device globals; no allocations allowed) ----------
__device__ float g_q[S_LEN * DIM];
__device__ float g_k[S_LEN * DIM];
__device__ float g_v[S_LEN * DIM];
__device__ float g_ao[S_LEN * DIM];

// ---------------- GEMM: C[M,Nn] = A[M,K] @ W[Nn,K]^T + bias -----------------
// BM=128, BN=128, BK=8, 256 threads, 8x8 per-thread microtile.
#define BM 128
#define BN 128
#define BK 8

__global__ __launch_bounds__(256, 2)
void gemm_bias_kernel(const float* __restrict__ A, const float* __restrict__ W,
                      const float* __restrict__ bias, float* __restrict__ C,
                      int M, int Nn, int K)
{
    __shared__ float As[BK][BM];
    __shared__ float Ws[BK][BN];

    const int bm = blockIdx.y * BM;
    const int bn = blockIdx.x * BN;
    const int tid = threadIdx.x;
    const int tr = tid >> 4;   // 0..15
    const int tc = tid & 15;   // 0..15

    const int la_row = tid >> 1;        // 0..127
    const int la_col = (tid & 1) * 4;   // 0 or 4

    float acc[8][8];
#pragma unroll
    for (int i = 0; i < 8; i++)
#pragma unroll
        for (int j = 0; j < 8; j++) acc[i][j] = 0.f;

    const float* Aptr = A + (size_t)(bm + la_row) * K + la_col;
    const float* Wptr = W + (size_t)(bn + la_row) * K + la_col;

    for (int k0 = 0; k0 < K; k0 += BK) {
        float4 av = *(const float4*)(Aptr + k0);
        float4 wv = *(const float4*)(Wptr + k0);
        __syncthreads();
        As[la_col + 0][la_row] = av.x;
        As[la_col + 1][la_row] = av.y;
        As[la_col + 2][la_row] = av.z;
        As[la_col + 3][la_row] = av.w;
        Ws[la_col + 0][la_row] = wv.x;
        Ws[la_col + 1][la_row] = wv.y;
        Ws[la_col + 2][la_row] = wv.z;
        Ws[la_col + 3][la_row] = wv.w;
        __syncthreads();
#pragma unroll
        for (int kk = 0; kk < BK; kk++) {
            float4 a0 = *(const float4*)&As[kk][tr * 8];
            float4 a1 = *(const float4*)&As[kk][tr * 8 + 4];
            float4 b0 = *(const float4*)&Ws[kk][tc * 8];
            float4 b1 = *(const float4*)&Ws[kk][tc * 8 + 4];
            float ra[8] = {a0.x, a0.y, a0.z, a0.w, a1.x, a1.y, a1.z, a1.w};
            float rb[8] = {b0.x, b0.y, b0.z, b0.w, b1.x, b1.y, b1.z, b1.w};
#pragma unroll
            for (int i = 0; i < 8; i++)
#pragma unroll
                for (int j = 0; j < 8; j++)
                    acc[i][j] += ra[i] * rb[j];
        }
    }

    // epilogue with bias
    float bb[8];
#pragma unroll
    for (int j = 0; j < 8; j++) bb[j] = bias[bn + tc * 8 + j];

#pragma unroll
    for (int i = 0; i < 8; i++) {
        float* crow = C + (size_t)(bm + tr * 8 + i) * Nn + bn + tc * 8;
        float4 s0 = {acc[i][0] + bb[0], acc[i][1] + bb[1], acc[i][2] + bb[2], acc[i][3] + bb[3]};
        float4 s1 = {acc[i][4] + bb[4], acc[i][5] + bb[5], acc[i][6] + bb[6], acc[i][7] + bb[7]};
        *(float4*)(crow + 0) = s0;
        *(float4*)(crow + 4) = s1;
    }
}

// ---------------- RMSNorm (over full DIM) + interleaved RoPE ----------------
__global__ __launch_bounds__(256)
void rms_rope_kernel(float* __restrict__ buf, const float* __restrict__ w,
                     const float* __restrict__ cosb, const float* __restrict__ sinb)
{
    const int row = blockIdx.x;
    float* p = buf + (size_t)row * DIM;
    const int tid = threadIdx.x;

    float ss = 0.f;
    for (int i = tid; i < DIM; i += 256) {
        float v = p[i];
        ss += v * v;
    }
#pragma unroll
    for (int off = 16; off > 0; off >>= 1)
        ss += __shfl_xor_sync(0xffffffffu, ss, off);

    __shared__ float red[8];
    __shared__ float sc;
    if ((tid & 31) == 0) red[tid >> 5] = ss;
    __syncthreads();
    if (tid == 0) {
        float t = 0.f;
#pragma unroll
        for (int i = 0; i < 8; i++) t += red[i];
        sc = rsqrtf(t / (float)DIM + 1e-6f);
    }
    __syncthreads();
    const float scale = sc;

    const float* crow = cosb + (size_t)row * HD;
    const float* srow = sinb + (size_t)row * HD;
    for (int pi = tid; pi < DIM / 2; pi += 256) {
        int i0 = 2 * pi;
        float2 xv = *(float2*)&p[i0];
        float e = xv.x * scale * w[i0];
        float o = xv.y * scale * w[i0 + 1];
        int dd = i0 & (HD - 1);
        float c = crow[dd];
        float s = srow[dd];
        float2 r;
        r.x = e * c - o * s;
        r.y = o * c + e * s;
        *(float2*)&p[i0] = r;
    }
}

// ---------------- Flash attention, fp32 SIMT ---------------------------------
// Tiles: 64 queries x 64 keys, D=128. 256 threads.
// smem: Qs(64x128 swz) + KVs(64x128 swz, shared K/V) + Ps(64x65) + stats.
#define BQ 64
#define BKEY 64
#define SMEM_FLOATS (BQ*HD + BKEY*HD + BQ*65 + 3*BQ)

__device__ __forceinline__ int swz(int j, int d) {
    return j * HD + (d ^ (4 * (j & 7)));
}

__global__ __launch_bounds__(256, 2)
void attn_kernel(const float* __restrict__ Q, const float* __restrict__ K,
                 const float* __restrict__ V, float* __restrict__ O,
                 const int* __restrict__ seq_lens)
{
    extern __shared__ float smem[];
    float* Qs   = smem;
    float* KVs  = Qs + BQ * HD;
    float* Ps   = KVs + BKEY * HD;
    float* m_sm = Ps + BQ * 65;
    float* f_sm = m_sm + BQ;
    float* l_sm = f_sm + BQ;

    const int qb = blockIdx.x;
    const int h  = blockIdx.y;
    const int tid = threadIdx.x;
    const int ty = tid >> 4;   // 0..15
    const int tx = tid & 15;   // 0..15

    const int seqlen = seq_lens[0];
    const int ntiles = (seqlen + BKEY - 1) / BKEY;
    const float qscale = 0.08838834764831845f; // 1/sqrt(128)

    // load Q tile (scaled, swizzled)
    {
        const float* src = Q + (size_t)(qb * BQ) * DIM + h * HD;
        for (int t = tid; t < BQ * HD / 4; t += 256) {
            int j = t >> 5;
            int d0 = (t & 31) * 4;
            float4 v = *(const float4*)(src + (size_t)j * DIM + d0);
            v.x *= qscale; v.y *= qscale; v.z *= qscale; v.w *= qscale;
            *(float4*)&Qs[swz(j, d0)] = v;
        }
    }
    if (tid < BQ) {
        m_sm[tid] = -INFINITY;
        l_sm[tid] = 0.f;
    }

    // output accumulator: row = tid/4, dims dbase..dbase+31
    const int orow  = tid >> 2;
    const int dbase = (tid & 3) * 32;
    float oacc[32];
#pragma unroll
    for (int t = 0; t < 32; t++) oacc[t] = 0.f;

    const int mk = 4 * (tx & 7);
    int mq[4];
#pragma unroll
    for (int i = 0; i < 4; i++) mq[i] = 4 * ((4 * ty + i) & 7);

    for (int kt = 0; kt < ntiles; kt++) {
        __syncthreads();  // protect KVs/Ps from previous phase3 readers

        // load K tile (swizzled)
        {
            const float* src = K + (size_t)(kt * BKEY) * DIM + h * HD;
            for (int t = tid; t < BKEY * HD / 4; t += 256) {
                int j = t >> 5;
                int d0 = (t & 31) * 4;
                float4 v = *(const float4*)(src + (size_t)j * DIM + d0);
                *(float4*)&KVs[swz(j, d0)] = v;
            }
        }
        __syncthreads();

        // ---- phase 1: scores + softmax partials ----
        float acc[4][4];
#pragma unroll
        for (int i = 0; i < 4; i++)
#pragma unroll
            for (int jj = 0; jj < 4; jj++) acc[i][jj] = 0.f;

#pragma unroll 4
        for (int d0 = 0; d0 < HD; d0 += 4) {
            float4 qv[4], kv[4];
#pragma unroll
            for (int i = 0; i < 4; i++)
                qv[i] = *(const float4*)&Qs[(4 * ty + i) * HD + (d0 ^ mq[i])];
#pragma unroll
            for (int jj = 0; jj < 4; jj++)
                kv[jj] = *(const float4*)&KVs[(tx + 16 * jj) * HD + (d0 ^ mk)];
#pragma unroll
            for (int i = 0; i < 4; i++)
#pragma unroll
                for (int jj = 0; jj < 4; jj++)
                    acc[i][jj] += qv[i].x * kv[jj].x + qv[i].y * kv[jj].y +
                                  qv[i].z * kv[jj].z + qv[i].w * kv[jj].w;
        }

        float mnew_k[4], fac_k[4], rs_k[4];
        const int gcol0 = kt * BKEY;
#pragma unroll
        for (int i = 0; i < 4; i++) {
            const int r = 4 * ty + i;
            float sij[4];
            float rowmax = -INFINITY;
#pragma unroll
            for (int jj = 0; jj < 4; jj++) {
                int gcol = gcol0 + tx + 16 * jj;
                float sv = (gcol < seqlen) ? acc[i][jj] : -1e30f;
                sij[jj] = sv;
                rowmax = fmaxf(rowmax, sv);
            }
#pragma unroll
            for (int off = 8; off > 0; off >>= 1)
                rowmax = fmaxf(rowmax, __shfl_xor_sync(0xffffffffu, rowmax, off));

            float mold = m_sm[r];
            float mnew = fmaxf(mold, rowmax);
            float rowsum = 0.f;
#pragma unroll
            for (int jj = 0; jj < 4; jj++) {
                float pv = __expf(sij[jj] - mnew);
                Ps[r * 65 + tx + 16 * jj] = pv;
                rowsum += pv;
            }
#pragma unroll
            for (int off = 8; off > 0; off >>= 1)
                rowsum += __shfl_xor_sync(0xffffffffu, rowsum, off);

            mnew_k[i] = mnew;
            fac_k[i]  = __expf(mold - mnew);
            rs_k[i]   = rowsum;
        }
        __syncthreads();

        // ---- phase 2: stats update (tx==0) + V load (all) ----
        if (tx == 0) {
#pragma unroll
            for (int i = 0; i < 4; i++) {
                const int r = 4 * ty + i;
                m_sm[r] = mnew_k[i];
                f_sm[r] = fac_k[i];
                l_sm[r] = l_sm[r] * fac_k[i] + rs_k[i];
            }
        }
        {
            const float* src = V + (size_t)(kt * BKEY) * DIM + h * HD;
            for (int t = tid; t < BKEY * HD / 4; t += 256) {
                int j = t >> 5;
                int d0 = (t & 31) * 4;
                float4 v = *(const float4*)(src + (size_t)j * DIM + d0);
                *(float4*)&KVs[swz(j, d0)] = v;
            }
        }
        __syncthreads();

        // ---- phase 3: O update ----
        const float f = f_sm[orow];
#pragma unroll
        for (int t = 0; t < 32; t++) oacc[t] *= f;

#pragma unroll 4
        for (int j = 0; j < BKEY; j++) {
            const float pj = Ps[orow * 65 + j];
            const int mv = 4 * (j & 7);
            const float* vrow = &KVs[j * HD];
#pragma unroll
            for (int t4 = 0; t4 < 8; t4++) {
                float4 vv = *(const float4*)&vrow[(dbase + 4 * t4) ^ mv];
                oacc[4 * t4 + 0] += pj * vv.x;
                oacc[4 * t4 + 1] += pj * vv.y;
                oacc[4 * t4 + 2] += pj * vv.z;
                oacc[4 * t4 + 3] += pj * vv.w;
            }
        }
    }

    // final normalize + store
    const float inv = 1.0f / l_sm[orow];
    float* dst = O + (size_t)(qb * BQ + orow) * DIM + h * HD + dbase;
#pragma unroll
    for (int t4 = 0; t4 < 8; t4++) {
        float4 st = {oacc[4 * t4 + 0] * inv, oacc[4 * t4 + 1] * inv,
                     oacc[4 * t4 + 2] * inv, oacc[4 * t4 + 3] * inv};
        *(float4*)(dst + 4 * t4) = st;
    }
}

// ---------------- launch ----------------------------------------------------
extern "C" void kernel_launch(void* const* d_in, const int* in_sizes, int n_in,
                              void* d_out, int out_size)
{
    const float* x    = (const float*)d_in[0];
    const float* Wq   = (const float*)d_in[1];
    const float* bq   = (const float*)d_in[2];
    const float* Wk   = (const float*)d_in[3];
    const float* bk   = (const float*)d_in[4];
    const float* Wv   = (const float*)d_in[5];
    const float* bv   = (const float*)d_in[6];
    const float* Wo   = (const float*)d_in[7];
    const float* bo   = (const float*)d_in[8];
    const float* nqw  = (const float*)d_in[9];
    const float* nkw  = (const float*)d_in[10];
    const float* cosb = (const float*)d_in[11];
    const float* sinb = (const float*)d_in[12];
    const int*   seql = (const int*)d_in[13];
    float* out = (float*)d_out;

    float *q, *k, *v, *ao;
    cudaGetSymbolAddress((void**)&q,  g_q);
    cudaGetSymbolAddress((void**)&k,  g_k);
    cudaGetSymbolAddress((void**)&v,  g_v);
    cudaGetSymbolAddress((void**)&ao, g_ao);

    dim3 gg(DIM / BN, S_LEN / BM);
    gemm_bias_kernel<<<gg, 256>>>(x, Wq, bq, q, S_LEN, DIM, DIM);
    gemm_bias_kernel<<<gg, 256>>>(x, Wk, bk, k, S_LEN, DIM, DIM);
    gemm_bias_kernel<<<gg, 256>>>(x, Wv, bv, v, S_LEN, DIM, DIM);

    rms_rope_kernel<<<S_LEN, 256>>>(q, nqw, cosb, sinb);
    rms_rope_kernel<<<S_LEN, 256>>>(k, nkw, cosb, sinb);

    static_assert(SMEM_FLOATS * 4 < 84000, "smem budget");
    cudaFuncSetAttribute(attn_kernel, cudaFuncAttributeMaxDynamicSharedMemorySize,
                         SMEM_FLOATS * 4);
    attn_kernel<<<dim3(S_LEN / BQ, NH), 256, SMEM_FLOATS * 4>>>(q, k, v, ao, seql);

    gemm_bias_kernel<<<gg, 256>>>(ao, Wo, bo, out, S_LEN, DIM, DIM);
}

// round 3
// speedup vs baseline: 1.2357x; 1.2357x over previous
#include <cuda_runtime.h>
#include <cuda_bf16.h>
#include <math.h>
#include <stdint.h>

#define S_LEN 3072
#define DIM   2048
#define NH    16
#define HD    128
#define K3    (3*DIM)   // 6144: [hi | hi | lo] x [hi | lo | hi]

// ---------------- scratch (device globals; no allocations allowed) ----------
__device__ __align__(16) float g_q [S_LEN * DIM];
__device__ __align__(16) float g_k [S_LEN * DIM];
__device__ __align__(16) float g_v [S_LEN * DIM];
__device__ __align__(16) float g_ao[S_LEN * DIM];
__device__ __align__(16) __nv_bfloat16 g_x3 [S_LEN * K3];
__device__ __align__(16) __nv_bfloat16 g_ao3[S_LEN * K3];
__device__ __align__(16) __nv_bfloat16 g_w3 [4][DIM * K3];

// ---------------- PTX helpers ----------------------------------------------
__device__ __forceinline__ uint32_t smem_u32(const void* p) {
    uint32_t a;
    asm("{ .reg .u64 t; cvta.to.shared.u64 t, %1; cvt.u32.u64 %0, t; }" : "=r"(a) : "l"(p));
    return a;
}
__device__ __forceinline__ void cp_async16(uint32_t saddr, const void* g) {
    asm volatile("cp.async.cg.shared.global [%0], [%1], 16;" :: "r"(saddr), "l"(g));
}
#define CP_COMMIT() asm volatile("cp.async.commit_group;" ::: "memory")
#define CP_WAIT2()  asm volatile("cp.async.wait_group 2;" ::: "memory")

__device__ __forceinline__ void ldmx4(uint32_t& r0, uint32_t& r1, uint32_t& r2, uint32_t& r3,
                                      uint32_t addr) {
    asm volatile("ldmatrix.sync.aligned.m8n8.x4.shared.b16 {%0,%1,%2,%3}, [%4];"
                 : "=r"(r0), "=r"(r1), "=r"(r2), "=r"(r3) : "r"(addr));
}
__device__ __forceinline__ void mma_bf16(float* c, const uint32_t* a, uint32_t b0, uint32_t b1) {
    asm volatile("mma.sync.aligned.m16n8k16.row.col.f32.bf16.bf16.f32 "
                 "{%0,%1,%2,%3}, {%4,%5,%6,%7}, {%8,%9}, {%0,%1,%2,%3};"
                 : "+f"(c[0]), "+f"(c[1]), "+f"(c[2]), "+f"(c[3])
                 : "r"(a[0]), "r"(a[1]), "r"(a[2]), "r"(a[3]), "r"(b0), "r"(b1));
}

// ---------------- split-bf16 conversion -------------------------------------
// mode 0 (activation): [hi | hi | lo]   mode 1 (weight): [hi | lo | hi]
__global__ __launch_bounds__(256)
void cvt3_kernel(const float* __restrict__ src, __nv_bfloat16* __restrict__ dst,
                 int nelem, int mode)
{
    int i = blockIdx.x * 256 + threadIdx.x;
    if (i >= nelem) return;
    float v = src[i];
    __nv_bfloat16 hi = __float2bfloat16(v);
    __nv_bfloat16 lo = __float2bfloat16(v - __bfloat162float(hi));
    int row = i >> 11;
    int c   = i & 2047;
    size_t base = (size_t)row * K3;
    if (mode == 0) {
        dst[base + c] = hi; dst[base + DIM + c] = hi; dst[base + 2*DIM + c] = lo;
    } else {
        dst[base + c] = hi; dst[base + DIM + c] = lo; dst[base + 2*DIM + c] = hi;
    }
}

// ---------------- mma.sync GEMM: C[M,Nn] = A3[M,K3] @ W3[Nn,K3]^T + bias ----
// CTA tile 128x128, BK=64 bf16, 4-stage cp.async pipeline, 8 warps of 64x32.
#define GBM 128
#define GBN 128
#define GBK 64
#define GSTAGES 4
#define GNITER (K3 / GBK)            // 96
#define TILE_B 16384                 // 128 rows * 128 bytes
#define SWZ(off) ((off) ^ (((off) >> 3) & 0x70))

__device__ __forceinline__ void g_load_stage(uint32_t sA, uint32_t sB,
    const __nv_bfloat16* __restrict__ A, const __nv_bfloat16* __restrict__ B,
    int bm, int bn, int kc, int tid)
{
#pragma unroll
    for (int i = 0; i < 4; i++) {
        int c = tid + i * 256;
        int row = c >> 3, cc = c & 7;
        int off = row * 128 + cc * 16;
        cp_async16(sA + SWZ(off), A + (size_t)(bm + row) * K3 + kc + cc * 8);
    }
#pragma unroll
    for (int i = 0; i < 4; i++) {
        int c = tid + i * 256;
        int row = c >> 3, cc = c & 7;
        int off = row * 128 + cc * 16;
        cp_async16(sB + SWZ(off), B + (size_t)(bn + row) * K3 + kc + cc * 8);
    }
}

__global__ __launch_bounds__(256, 1)
void gemm_mma_kernel(const __nv_bfloat16* __restrict__ A,
                     const __nv_bfloat16* __restrict__ B,
                     const float* __restrict__ bias, float* __restrict__ C, int Nn)
{
    extern __shared__ __align__(1024) char smem[];
    const uint32_t sb = smem_u32(smem);
    const uint32_t sAb = sb;
    const uint32_t sBb = sb + GSTAGES * TILE_B;

    const int tid = threadIdx.x;
    const int wid = tid >> 5, lane = tid & 31;
    const int bm = blockIdx.y * GBM, bn = blockIdx.x * GBN;
    const int wm = (wid & 1) * 64;
    const int wn = (wid >> 1) * 32;

    // ldmatrix lane geometry
    const int a_row = lane & 15;            // row within 16-row tile
    const int a_kh  = (lane >> 4) * 16;     // k-half byte offset
    const int b_row = (lane & 7) + ((lane >> 4) << 3);  // n within 16
    const int b_kh  = ((lane >> 3) & 1) * 16;

    float acc[4][4][4];
#pragma unroll
    for (int mt = 0; mt < 4; mt++)
#pragma unroll
        for (int nt = 0; nt < 4; nt++)
#pragma unroll
            for (int r = 0; r < 4; r++) acc[mt][nt][r] = 0.f;

    // prologue: stages 0..2
#pragma unroll
    for (int s = 0; s < GSTAGES - 1; s++) {
        g_load_stage(sAb + s * TILE_B, sBb + s * TILE_B, A, B, bm, bn, s * GBK, tid);
        CP_COMMIT();
    }

    // precompute per-lane swizzled base addresses (row fixed per lane)
    uint32_t a_base[4], b_base[2];
#pragma unroll
    for (int mt = 0; mt < 4; mt++) {
        int row = wm + mt * 16 + a_row;
        a_base[mt] = row * 128 + ((row & 7) * 16);   // store xor mask folded via ^ later
    }
#pragma unroll
    for (int np = 0; np < 2; np++) {
        int row = wn + np * 16 + b_row;
        b_base[np] = row * 128 + ((row & 7) * 16);
    }
    // note: addr = base_rowstart + (col ^ xmask); we keep rowstart and xmask
    // separately: a_base = row*128, xmask = (row&7)*16
    uint32_t a_xm[4], b_xm[2];
#pragma unroll
    for (int mt = 0; mt < 4; mt++) {
        int row = wm + mt * 16 + a_row;
        a_base[mt] = row * 128;
        a_xm[mt] = (row & 7) * 16;
    }
#pragma unroll
    for (int np = 0; np < 2; np++) {
        int row = wn + np * 16 + b_row;
        b_base[np] = row * 128;
        b_xm[np] = (row & 7) * 16;
    }

    for (int it = 0; it < GNITER; it++) {
        CP_WAIT2();
        __syncthreads();
        const uint32_t sA = sAb + (it & 3) * TILE_B;
        const uint32_t sB = sBb + (it & 3) * TILE_B;

#pragma unroll
        for (int ks = 0; ks < 4; ks++) {
            const uint32_t kbyte = ks * 32;
            uint32_t af[4][4];
#pragma unroll
            for (int mt = 0; mt < 4; mt++)
                ldmx4(af[mt][0], af[mt][1], af[mt][2], af[mt][3],
                      sA + a_base[mt] + ((kbyte + a_kh) ^ a_xm[mt]));
            uint32_t bfr[2][4];
#pragma unroll
            for (int np = 0; np < 2; np++)
                ldmx4(bfr[np][0], bfr[np][1], bfr[np][2], bfr[np][3],
                      sB + b_base[np] + ((kbyte + b_kh) ^ b_xm[np]));
#pragma unroll
            for (int mt = 0; mt < 4; mt++)
#pragma unroll
                for (int nt = 0; nt < 4; nt++)
                    mma_bf16(acc[mt][nt], af[mt],
                             bfr[nt >> 1][(nt & 1) * 2], bfr[nt >> 1][(nt & 1) * 2 + 1]);
        }

        const int li = it + GSTAGES - 1;
        if (li < GNITER)
            g_load_stage(sAb + (li & 3) * TILE_B, sBb + (li & 3) * TILE_B,
                         A, B, bm, bn, li * GBK, tid);
        CP_COMMIT();
    }

    // epilogue with bias
    const int tq = lane >> 2, tr4 = lane & 3;
#pragma unroll
    for (int mt = 0; mt < 4; mt++) {
#pragma unroll
        for (int nt = 0; nt < 4; nt++) {
            const int row = bm + wm + mt * 16 + tq;
            const int col = bn + wn + nt * 8 + tr4 * 2;
            const float b0 = bias[col], b1 = bias[col + 1];
            float2 v0 = {acc[mt][nt][0] + b0, acc[mt][nt][1] + b1};
            float2 v1 = {acc[mt][nt][2] + b0, acc[mt][nt][3] + b1};
            *(float2*)&C[(size_t)row * Nn + col]       = v0;
            *(float2*)&C[(size_t)(row + 8) * Nn + col] = v1;
        }
    }
}

// ---------------- RMSNorm + interleaved RoPE --------------------------------
__global__ __launch_bounds__(256)
void rms_rope_kernel(float* __restrict__ buf, const float* __restrict__ w,
                     const float* __restrict__ cosb, const float* __restrict__ sinb)
{
    const int row = blockIdx.x;
    float* p = buf + (size_t)row * DIM;
    const int tid = threadIdx.x;

    float ss = 0.f;
    for (int i = tid; i < DIM; i += 256) { float v = p[i]; ss += v * v; }
#pragma unroll
    for (int off = 16; off > 0; off >>= 1) ss += __shfl_xor_sync(0xffffffffu, ss, off);

    __shared__ float red[8];
    __shared__ float sc;
    if ((tid & 31) == 0) red[tid >> 5] = ss;
    __syncthreads();
    if (tid == 0) {
        float t = 0.f;
#pragma unroll
        for (int i = 0; i < 8; i++) t += red[i];
        sc = rsqrtf(t / (float)DIM + 1e-6f);
    }
    __syncthreads();
    const float scale = sc;

    const float* crow = cosb + (size_t)row * HD;
    const float* srow = sinb + (size_t)row * HD;
    for (int pi = tid; pi < DIM / 2; pi += 256) {
        int i0 = 2 * pi;
        float2 xv = *(float2*)&p[i0];
        float e = xv.x * scale * w[i0];
        float o = xv.y * scale * w[i0 + 1];
        int dd = i0 & (HD - 1);
        float c = crow[dd], s = srow[dd];
        float2 r;
        r.x = e * c - o * s;
        r.y = o * c + e * s;
        *(float2*)&p[i0] = r;
    }
}

// ---------------- Flash attention, fp32 SIMT --------------------------------
#define BQ 64
#define BKEY 64
#define SMEM_FLOATS (BQ*HD + BKEY*HD + BQ*65 + 3*BQ)

__device__ __forceinline__ int swz(int j, int d) {
    return j * HD + (d ^ (4 * (j & 7)));
}

__global__ __launch_bounds__(256, 2)
void attn_kernel(const float* __restrict__ Q, const float* __restrict__ K,
                 const float* __restrict__ V, float* __restrict__ O,
                 const int* __restrict__ seq_lens)
{
    extern __shared__ float smemf[];
    float* Qs   = smemf;
    float* KVs  = Qs + BQ * HD;
    float* Ps   = KVs + BKEY * HD;
    float* m_sm = Ps + BQ * 65;
    float* f_sm = m_sm + BQ;
    float* l_sm = f_sm + BQ;

    const int qb = blockIdx.x;
    const int h  = blockIdx.y;
    const int tid = threadIdx.x;
    const int ty = tid >> 4;
    const int tx = tid & 15;

    const int seqlen = seq_lens[0];
    const int ntiles = (seqlen + BKEY - 1) / BKEY;
    const float qscale = 0.08838834764831845f;

    {
        const float* src = Q + (size_t)(qb * BQ) * DIM + h * HD;
        for (int t = tid; t < BQ * HD / 4; t += 256) {
            int j = t >> 5;
            int d0 = (t & 31) * 4;
            float4 v = *(const float4*)(src + (size_t)j * DIM + d0);
            v.x *= qscale; v.y *= qscale; v.z *= qscale; v.w *= qscale;
            *(float4*)&Qs[swz(j, d0)] = v;
        }
    }
    if (tid < BQ) { m_sm[tid] = -INFINITY; l_sm[tid] = 0.f; }

    const int orow  = tid >> 2;
    const int dbase = (tid & 3) * 32;
    float oacc[32];
#pragma unroll
    for (int t = 0; t < 32; t++) oacc[t] = 0.f;

    const int mk = 4 * (tx & 7);
    int mq[4];
#pragma unroll
    for (int i = 0; i < 4; i++) mq[i] = 4 * ((4 * ty + i) & 7);

    for (int kt = 0; kt < ntiles; kt++) {
        __syncthreads();
        {
            const float* src = K + (size_t)(kt * BKEY) * DIM + h * HD;
            for (int t = tid; t < BKEY * HD / 4; t += 256) {
                int j = t >> 5;
                int d0 = (t & 31) * 4;
                float4 v = *(const float4*)(src + (size_t)j * DIM + d0);
                *(float4*)&KVs[swz(j, d0)] = v;
            }
        }
        __syncthreads();

        float acc[4][4];
#pragma unroll
        for (int i = 0; i < 4; i++)
#pragma unroll
            for (int jj = 0; jj < 4; jj++) acc[i][jj] = 0.f;

#pragma unroll 4
        for (int d0 = 0; d0 < HD; d0 += 4) {
            float4 qv[4], kv[4];
#pragma unroll
            for (int i = 0; i < 4; i++)
                qv[i] = *(const float4*)&Qs[(4 * ty + i) * HD + (d0 ^ mq[i])];
#pragma unroll
            for (int jj = 0; jj < 4; jj++)
                kv[jj] = *(const float4*)&KVs[(tx + 16 * jj) * HD + (d0 ^ mk)];
#pragma unroll
            for (int i = 0; i < 4; i++)
#pragma unroll
                for (int jj = 0; jj < 4; jj++)
                    acc[i][jj] += qv[i].x * kv[jj].x + qv[i].y * kv[jj].y +
                                  qv[i].z * kv[jj].z + qv[i].w * kv[jj].w;
        }

        float mnew_k[4], fac_k[4], rs_k[4];
        const int gcol0 = kt * BKEY;
#pragma unroll
        for (int i = 0; i < 4; i++) {
            const int r = 4 * ty + i;
            float sij[4];
            float rowmax = -INFINITY;
#pragma unroll
            for (int jj = 0; jj < 4; jj++) {
                int gcol = gcol0 + tx + 16 * jj;
                float sv = (gcol < seqlen) ? acc[i][jj] : -1e30f;
                sij[jj] = sv;
                rowmax = fmaxf(rowmax, sv);
            }
#pragma unroll
            for (int off = 8; off > 0; off >>= 1)
                rowmax = fmaxf(rowmax, __shfl_xor_sync(0xffffffffu, rowmax, off));

            float mold = m_sm[r];
            float mnew = fmaxf(mold, rowmax);
            float rowsum = 0.f;
#pragma unroll
            for (int jj = 0; jj < 4; jj++) {
                float pv = __expf(sij[jj] - mnew);
                Ps[r * 65 + tx + 16 * jj] = pv;
                rowsum += pv;
            }
#pragma unroll
            for (int off = 8; off > 0; off >>= 1)
                rowsum += __shfl_xor_sync(0xffffffffu, rowsum, off);

            mnew_k[i] = mnew;
            fac_k[i]  = __expf(mold - mnew);
            rs_k[i]   = rowsum;
        }
        __syncthreads();

        if (tx == 0) {
#pragma unroll
            for (int i = 0; i < 4; i++) {
                const int r = 4 * ty + i;
                m_sm[r] = mnew_k[i];
                f_sm[r] = fac_k[i];
                l_sm[r] = l_sm[r] * fac_k[i] + rs_k[i];
            }
        }
        {
            const float* src = V + (size_t)(kt * BKEY) * DIM + h * HD;
            for (int t = tid; t < BKEY * HD / 4; t += 256) {
                int j = t >> 5;
                int d0 = (t & 31) * 4;
                float4 v = *(const float4*)(src + (size_t)j * DIM + d0);
                *(float4*)&KVs[swz(j, d0)] = v;
            }
        }
        __syncthreads();

        const float f = f_sm[orow];
#pragma unroll
        for (int t = 0; t < 32; t++) oacc[t] *= f;

#pragma unroll 4
        for (int j = 0; j < BKEY; j++) {
            const float pj = Ps[orow * 65 + j];
            const int mv = 4 * (j & 7);
            const float* vrow = &KVs[j * HD];
#pragma unroll
            for (int t4 = 0; t4 < 8; t4++) {
                float4 vv = *(const float4*)&vrow[(dbase + 4 * t4) ^ mv];
                oacc[4 * t4 + 0] += pj * vv.x;
                oacc[4 * t4 + 1] += pj * vv.y;
                oacc[4 * t4 + 2] += pj * vv.z;
                oacc[4 * t4 + 3] += pj * vv.w;
            }
        }
    }

    const float inv = 1.0f / l_sm[orow];
    float* dst = O + (size_t)(qb * BQ + orow) * DIM + h * HD + dbase;
#pragma unroll
    for (int t4 = 0; t4 < 8; t4++) {
        float4 st = {oacc[4 * t4 + 0] * inv, oacc[4 * t4 + 1] * inv,
                     oacc[4 * t4 + 2] * inv, oacc[4 * t4 + 3] * inv};
        *(float4*)(dst + 4 * t4) = st;
    }
}

// ---------------- launch ----------------------------------------------------
extern "C" void kernel_launch(void* const* d_in, const int* in_sizes, int n_in,
                              void* d_out, int out_size)
{
    const float* x    = (const float*)d_in[0];
    const float* Wq   = (const float*)d_in[1];
    const float* bq   = (const float*)d_in[2];
    const float* Wk   = (const float*)d_in[3];
    const float* bk   = (const float*)d_in[4];
    const float* Wv   = (const float*)d_in[5];
    const float* bv   = (const float*)d_in[6];
    const float* Wo   = (const float*)d_in[7];
    const float* bo   = (const float*)d_in[8];
    const float* nqw  = (const float*)d_in[9];
    const float* nkw  = (const float*)d_in[10];
    const float* cosb = (const float*)d_in[11];
    const float* sinb = (const float*)d_in[12];
    const int*   seql = (const int*)d_in[13];
    float* out = (float*)d_out;

    float *q, *k, *v, *ao;
    __nv_bfloat16 *x3, *ao3, *w3;
    cudaGetSymbolAddress((void**)&q,   g_q);
    cudaGetSymbolAddress((void**)&k,   g_k);
    cudaGetSymbolAddress((void**)&v,   g_v);
    cudaGetSymbolAddress((void**)&ao,  g_ao);
    cudaGetSymbolAddress((void**)&x3,  g_x3);
    cudaGetSymbolAddress((void**)&ao3, g_ao3);
    cudaGetSymbolAddress((void**)&w3,  g_w3);

    const int SMEM_G = GSTAGES * TILE_B * 2;  // 131072
    cudaFuncSetAttribute(gemm_mma_kernel, cudaFuncAttributeMaxDynamicSharedMemorySize,
                         SMEM_G);

    const int nx = S_LEN * DIM, nw = DIM * DIM;
    cvt3_kernel<<<(nx + 255) / 256, 256>>>(x,  x3, nx, 0);
    cvt3_kernel<<<(nw + 255) / 256, 256>>>(Wq, w3 + 0 * (size_t)DIM * K3, nw, 1);
    cvt3_kernel<<<(nw + 255) / 256, 256>>>(Wk, w3 + 1 * (size_t)DIM * K3, nw, 1);
    cvt3_kernel<<<(nw + 255) / 256, 256>>>(Wv, w3 + 2 * (size_t)DIM * K3, nw, 1);
    cvt3_kernel<<<(nw + 255) / 256, 256>>>(Wo, w3 + 3 * (size_t)DIM * K3, nw, 1);

    dim3 gg(DIM / GBN, S_LEN / GBM);
    gemm_mma_kernel<<<gg, 256, SMEM_G>>>(x3, w3 + 0 * (size_t)DIM * K3, bq, q, DIM);
    gemm_mma_kernel<<<gg, 256, SMEM_G>>>(x3, w3 + 1 * (size_t)DIM * K3, bk, k, DIM);
    gemm_mma_kernel<<<gg, 256, SMEM_G>>>(x3, w3 + 2 * (size_t)DIM * K3, bv, v, DIM);

    rms_rope_kernel<<<S_LEN, 256>>>(q, nqw, cosb, sinb);
    rms_rope_kernel<<<S_LEN, 256>>>(k, nkw, cosb, sinb);

    cudaFuncSetAttribute(attn_kernel, cudaFuncAttributeMaxDynamicSharedMemorySize,
                         SMEM_FLOATS * 4);
    attn_kernel<<<dim3(S_LEN / BQ, NH), 256, SMEM_FLOATS * 4>>>(q, k, v, ao, seql);

    cvt3_kernel<<<(nx + 255) / 256, 256>>>(ao, ao3, nx, 0);
    gemm_mma_kernel<<<gg, 256, SMEM_G>>>(ao3, w3 + 3 * (size_t)DIM * K3, bo, out, DIM);
}

// round 4
// speedup vs baseline: 6.9039x; 5.5870x over previous
#include <cuda_runtime.h>
#include <cuda_bf16.h>
#include <math.h>
#include <stdint.h>

#define S_LEN 3072
#define DIM   2048
#define NH    16
#define HD    128
#define K3    (3*DIM)   // 6144: [hi | hi | lo] x [hi | lo | hi]

// ---------------- scratch (device globals; no allocations allowed) ----------
__device__ __align__(16) float g_q [S_LEN * DIM];
__device__ __align__(16) float g_k [S_LEN * DIM];
__device__ __align__(16) float g_v [S_LEN * DIM];
__device__ __align__(16) float g_ao[S_LEN * DIM];
__device__ __align__(16) __nv_bfloat16 g_x3 [S_LEN * K3];
__device__ __align__(16) __nv_bfloat16 g_ao3[S_LEN * K3];
__device__ __align__(16) __nv_bfloat16 g_w3 [4][DIM * K3];
__device__ __align__(16) __nv_bfloat16 g_qs [NH * S_LEN * 256];   // [h][s][hi128|lo128]
__device__ __align__(16) __nv_bfloat16 g_ks [NH * S_LEN * 256];
__device__ __align__(16) __nv_bfloat16 g_vt [NH * 256 * S_LEN];   // [h][d:hi,d+128:lo][s]

// ---------------- PTX helpers ----------------------------------------------
__device__ __forceinline__ uint32_t smem_u32(const void* p) {
    uint32_t a;
    asm("{ .reg .u64 t; cvta.to.shared.u64 t, %1; cvt.u32.u64 %0, t; }" : "=r"(a) : "l"(p));
    return a;
}
__device__ __forceinline__ void cp_async16(uint32_t saddr, const void* g) {
    asm volatile("cp.async.cg.shared.global [%0], [%1], 16;" :: "r"(saddr), "l"(g));
}
#define CP_COMMIT() asm volatile("cp.async.commit_group;" ::: "memory")
#define CP_WAIT2()  asm volatile("cp.async.wait_group 2;" ::: "memory")
#define CP_WAIT1()  asm volatile("cp.async.wait_group 1;" ::: "memory")
#define CP_WAIT0()  asm volatile("cp.async.wait_group 0;" ::: "memory")

__device__ __forceinline__ void ldmx4(uint32_t& r0, uint32_t& r1, uint32_t& r2, uint32_t& r3,
                                      uint32_t addr) {
    asm volatile("ldmatrix.sync.aligned.m8n8.x4.shared.b16 {%0,%1,%2,%3}, [%4];"
                 : "=r"(r0), "=r"(r1), "=r"(r2), "=r"(r3) : "r"(addr));
}
__device__ __forceinline__ void mma_bf16(float* c, const uint32_t* a, uint32_t b0, uint32_t b1) {
    asm volatile("mma.sync.aligned.m16n8k16.row.col.f32.bf16.bf16.f32 "
                 "{%0,%1,%2,%3}, {%4,%5,%6,%7}, {%8,%9}, {%0,%1,%2,%3};"
                 : "+f"(c[0]), "+f"(c[1]), "+f"(c[2]), "+f"(c[3])
                 : "r"(a[0]), "r"(a[1]), "r"(a[2]), "r"(a[3]), "r"(b0), "r"(b1));
}
__device__ __forceinline__ void split2(float a, float b, uint32_t& hi, uint32_t& lo) {
    __nv_bfloat16 ha = __float2bfloat16(a), hb = __float2bfloat16(b);
    __nv_bfloat16 la = __float2bfloat16(a - __bfloat162float(ha));
    __nv_bfloat16 lb = __float2bfloat16(b - __bfloat162float(hb));
    __nv_bfloat162 H; H.x = ha; H.y = hb;
    __nv_bfloat162 L; L.x = la; L.y = lb;
    hi = *reinterpret_cast<uint32_t*>(&H);
    lo = *reinterpret_cast<uint32_t*>(&L);
}

// ---------------- split-bf16 conversion (for GEMM inputs) -------------------
__global__ __launch_bounds__(256)
void cvt3_kernel(const float* __restrict__ src, __nv_bfloat16* __restrict__ dst,
                 int nelem, int mode)
{
    int i = blockIdx.x * 256 + threadIdx.x;
    if (i >= nelem) return;
    float v = src[i];
    __nv_bfloat16 hi = __float2bfloat16(v);
    __nv_bfloat16 lo = __float2bfloat16(v - __bfloat162float(hi));
    int row = i >> 11;
    int c   = i & 2047;
    size_t base = (size_t)row * K3;
    if (mode == 0) {
        dst[base + c] = hi; dst[base + DIM + c] = hi; dst[base + 2*DIM + c] = lo;
    } else {
        dst[base + c] = hi; dst[base + DIM + c] = lo; dst[base + 2*DIM + c] = hi;
    }
}

// ---------------- mma.sync GEMM (unchanged from R3) -------------------------
#define GBM 128
#define GBN 128
#define GBK 64
#define GSTAGES 4
#define GNITER (K3 / GBK)
#define TILE_B 16384
#define SWZ(off) ((off) ^ (((off) >> 3) & 0x70))

__device__ __forceinline__ void g_load_stage(uint32_t sA, uint32_t sB,
    const __nv_bfloat16* __restrict__ A, const __nv_bfloat16* __restrict__ B,
    int bm, int bn, int kc, int tid)
{
#pragma unroll
    for (int i = 0; i < 4; i++) {
        int c = tid + i * 256;
        int row = c >> 3, cc = c & 7;
        int off = row * 128 + cc * 16;
        cp_async16(sA + SWZ(off), A + (size_t)(bm + row) * K3 + kc + cc * 8);
    }
#pragma unroll
    for (int i = 0; i < 4; i++) {
        int c = tid + i * 256;
        int row = c >> 3, cc = c & 7;
        int off = row * 128 + cc * 16;
        cp_async16(sB + SWZ(off), B + (size_t)(bn + row) * K3 + kc + cc * 8);
    }
}

__global__ __launch_bounds__(256, 1)
void gemm_mma_kernel(const __nv_bfloat16* __restrict__ A,
                     const __nv_bfloat16* __restrict__ B,
                     const float* __restrict__ bias, float* __restrict__ C, int Nn)
{
    extern __shared__ __align__(1024) char smem[];
    const uint32_t sb = smem_u32(smem);
    const uint32_t sAb = sb;
    const uint32_t sBb = sb + GSTAGES * TILE_B;

    const int tid = threadIdx.x;
    const int wid = tid >> 5, lane = tid & 31;
    const int bm = blockIdx.y * GBM, bn = blockIdx.x * GBN;
    const int wm = (wid & 1) * 64;
    const int wn = (wid >> 1) * 32;

    const int a_row = lane & 15;
    const int a_kh  = (lane >> 4) * 16;
    const int b_row = (lane & 7) + ((lane >> 4) << 3);
    const int b_kh  = ((lane >> 3) & 1) * 16;

    float acc[4][4][4];
#pragma unroll
    for (int mt = 0; mt < 4; mt++)
#pragma unroll
        for (int nt = 0; nt < 4; nt++)
#pragma unroll
            for (int r = 0; r < 4; r++) acc[mt][nt][r] = 0.f;

#pragma unroll
    for (int s = 0; s < GSTAGES - 1; s++) {
        g_load_stage(sAb + s * TILE_B, sBb + s * TILE_B, A, B, bm, bn, s * GBK, tid);
        CP_COMMIT();
    }

    uint32_t a_base[4], b_base[2], a_xm[4], b_xm[2];
#pragma unroll
    for (int mt = 0; mt < 4; mt++) {
        int row = wm + mt * 16 + a_row;
        a_base[mt] = row * 128;
        a_xm[mt] = (row & 7) * 16;
    }
#pragma unroll
    for (int np = 0; np < 2; np++) {
        int row = wn + np * 16 + b_row;
        b_base[np] = row * 128;
        b_xm[np] = (row & 7) * 16;
    }

    for (int it = 0; it < GNITER; it++) {
        CP_WAIT2();
        __syncthreads();
        const uint32_t sA = sAb + (it & 3) * TILE_B;
        const uint32_t sB = sBb + (it & 3) * TILE_B;

#pragma unroll
        for (int ks = 0; ks < 4; ks++) {
            const uint32_t kbyte = ks * 32;
            uint32_t af[4][4];
#pragma unroll
            for (int mt = 0; mt < 4; mt++)
                ldmx4(af[mt][0], af[mt][1], af[mt][2], af[mt][3],
                      sA + a_base[mt] + ((kbyte + a_kh) ^ a_xm[mt]));
            uint32_t bfr[2][4];
#pragma unroll
            for (int np = 0; np < 2; np++)
                ldmx4(bfr[np][0], bfr[np][1], bfr[np][2], bfr[np][3],
                      sB + b_base[np] + ((kbyte + b_kh) ^ b_xm[np]));
#pragma unroll
            for (int mt = 0; mt < 4; mt++)
#pragma unroll
                for (int nt = 0; nt < 4; nt++)
                    mma_bf16(acc[mt][nt], af[mt],
                             bfr[nt >> 1][(nt & 1) * 2], bfr[nt >> 1][(nt & 1) * 2 + 1]);
        }

        const int li = it + GSTAGES - 1;
        if (li < GNITER)
            g_load_stage(sAb + (li & 3) * TILE_B, sBb + (li & 3) * TILE_B,
                         A, B, bm, bn, li * GBK, tid);
        CP_COMMIT();
    }

    const int tq = lane >> 2, tr4 = lane & 3;
#pragma unroll
    for (int mt = 0; mt < 4; mt++) {
#pragma unroll
        for (int nt = 0; nt < 4; nt++) {
            const int row = bm + wm + mt * 16 + tq;
            const int col = bn + wn + nt * 8 + tr4 * 2;
            const float b0 = bias[col], b1 = bias[col + 1];
            float2 v0 = {acc[mt][nt][0] + b0, acc[mt][nt][1] + b1};
            float2 v1 = {acc[mt][nt][2] + b0, acc[mt][nt][3] + b1};
            *(float2*)&C[(size_t)row * Nn + col]       = v0;
            *(float2*)&C[(size_t)(row + 8) * Nn + col] = v1;
        }
    }
}

// ---------------- RMSNorm + RoPE + hi/lo split -> [NH][S][256] bf16 ---------
__global__ __launch_bounds__(256)
void rms_rope_split_kernel(const float* __restrict__ src, const float* __restrict__ w,
                           const float* __restrict__ cosb, const float* __restrict__ sinb,
                           __nv_bfloat16* __restrict__ dst, float outscale)
{
    const int row = blockIdx.x;
    const float* p = src + (size_t)row * DIM;
    const int tid = threadIdx.x;

    float ss = 0.f;
    for (int i = tid; i < DIM; i += 256) { float v = p[i]; ss += v * v; }
#pragma unroll
    for (int off = 16; off > 0; off >>= 1) ss += __shfl_xor_sync(0xffffffffu, ss, off);

    __shared__ float red[8];
    __shared__ float sc;
    if ((tid & 31) == 0) red[tid >> 5] = ss;
    __syncthreads();
    if (tid == 0) {
        float t = 0.f;
#pragma unroll
        for (int i = 0; i < 8; i++) t += red[i];
        sc = rsqrtf(t / (float)DIM + 1e-6f);
    }
    __syncthreads();
    const float scale = sc;

    const float* crow = cosb + (size_t)row * HD;
    const float* srow = sinb + (size_t)row * HD;
    for (int pi = tid; pi < DIM / 2; pi += 256) {
        int i0 = 2 * pi;
        int h = i0 >> 7;
        int d = i0 & (HD - 1);
        float2 xv = *(const float2*)&p[i0];
        float e = xv.x * scale * w[i0];
        float o = xv.y * scale * w[i0 + 1];
        float c = crow[d], s = srow[d];
        float rx = (e * c - o * s) * outscale;
        float ry = (o * c + e * s) * outscale;
        uint32_t hi, lo;
        split2(rx, ry, hi, lo);
        __nv_bfloat16* base = dst + (size_t)h * S_LEN * 256 + (size_t)row * 256;
        *(uint32_t*)&base[d]       = hi;
        *(uint32_t*)&base[128 + d] = lo;
    }
}

// ---------------- V transpose + split -> [NH][256][S] bf16 ------------------
__global__ __launch_bounds__(256)
void vsplit_t_kernel(const float* __restrict__ v, __nv_bfloat16* __restrict__ vt)
{
    __shared__ float tile[32][33];
    const int s0 = blockIdx.x * 32;
    const int c0 = blockIdx.y * 32;
    const int tx = threadIdx.x & 31;
    const int ty = threadIdx.x >> 5;   // 0..7

#pragma unroll
    for (int i = 0; i < 4; i++) {
        int r = ty + i * 8;
        tile[r][tx] = v[(size_t)(s0 + r) * DIM + c0 + tx];
    }
    __syncthreads();
#pragma unroll
    for (int i = 0; i < 4; i++) {
        int dr = ty + i * 8;
        int dg = c0 + dr;
        int h = dg >> 7, d = dg & 127;
        float val = tile[tx][dr];
        __nv_bfloat16 hi = __float2bfloat16(val);
        __nv_bfloat16 lo = __float2bfloat16(val - __bfloat162float(hi));
        size_t base = (size_t)h * 256 * S_LEN;
        vt[base + (size_t)d * S_LEN + s0 + tx]         = hi;
        vt[base + (size_t)(d + 128) * S_LEN + s0 + tx] = lo;
    }
}

// ---------------- tensor-core flash attention -------------------------------
// 128 q-rows/CTA, 8 warps x 16 rows, 64-key tiles, double-buffered cp.async.
#define Q_SM_BYTES  (128 * 512)     // 64 KB (hi|lo 256 bf16/row)
#define K_SM_BYTES  (64 * 512)      // 32 KB
#define V_SM_BYTES  (256 * 128)     // 32 KB (hi rows 0-127, lo rows 128-255)
#define KV_ST       (K_SM_BYTES + V_SM_BYTES)
#define ATTN_SMEM   (Q_SM_BYTES + 2 * KV_ST)   // 196608

__device__ __forceinline__ void attn_load_kv(uint32_t kvb,
    const __nv_bfloat16* __restrict__ ksrc0, const __nv_bfloat16* __restrict__ vsrc0,
    int kt, int tid)
{
    const __nv_bfloat16* ksrc = ksrc0 + (size_t)kt * 64 * 256;
#pragma unroll
    for (int u = 0; u < 8; u++) {
        int c = tid + u * 256;
        int r = c >> 5, ch = c & 31;
        cp_async16(kvb + r * 512 + ((ch ^ (r & 7)) << 4), ksrc + (size_t)r * 256 + ch * 8);
    }
    const __nv_bfloat16* vsrc = vsrc0 + kt * 64;
    const uint32_t vb = kvb + K_SM_BYTES;
#pragma unroll
    for (int u = 0; u < 8; u++) {
        int c = tid + u * 256;
        int r = c >> 3, ch = c & 7;
        cp_async16(vb + r * 128 + ((ch ^ (r & 7)) << 4), vsrc + (size_t)r * S_LEN + ch * 8);
    }
}

__global__ __launch_bounds__(256, 1)
void attn_mma_kernel(const __nv_bfloat16* __restrict__ qs,
                     const __nv_bfloat16* __restrict__ ks,
                     const __nv_bfloat16* __restrict__ vt,
                     float* __restrict__ O, const int* __restrict__ seq_lens)
{
    extern __shared__ __align__(1024) char smem[];
    const uint32_t sb = smem_u32(smem);
    const uint32_t qsm = sb;
    const int tid = threadIdx.x, lane = tid & 31, wid = tid >> 5;
    const int qb = blockIdx.x, h = blockIdx.y;

    const int seqlen = seq_lens[0];
    const int ntiles = (seqlen + 63) >> 6;

    const __nv_bfloat16* qsrc  = qs + ((size_t)h * S_LEN + qb * 128) * 256;
    const __nv_bfloat16* ksrc0 = ks + (size_t)h * S_LEN * 256;
    const __nv_bfloat16* vsrc0 = vt + (size_t)h * 256 * S_LEN;

    // Q tile load (swizzled, 512B rows)
#pragma unroll
    for (int u = 0; u < 16; u++) {
        int c = tid + u * 256;
        int r = c >> 5, ch = c & 31;
        cp_async16(qsm + r * 512 + ((ch ^ (r & 7)) << 4), qsrc + (size_t)r * 256 + ch * 8);
    }
    attn_load_kv(sb + Q_SM_BYTES, ksrc0, vsrc0, 0, tid);
    CP_COMMIT();

    // fragment geometry
    const int a_row = wid * 16 + (lane & 15);
    const uint32_t a_off = a_row * 512;
    const int a_x = a_row & 7;
    const int a_k16 = lane >> 4;               // 0/1 chunk
    const int b_row = (lane & 7) + ((lane >> 4) << 3);
    const int b_k16 = (lane >> 3) & 1;

    uint32_t kb_off[4]; int kb_x[4];
#pragma unroll
    for (int np = 0; np < 4; np++) {
        int row = np * 16 + b_row;
        kb_off[np] = row * 512; kb_x[np] = row & 7;
    }
    uint32_t vb_off[8]; int vb_x[8];
#pragma unroll
    for (int np = 0; np < 8; np++) {
        int row = np * 16 + b_row;
        vb_off[np] = row * 128; vb_x[np] = row & 7;
    }

    float o[16][4];
#pragma unroll
    for (int nt = 0; nt < 16; nt++)
#pragma unroll
        for (int c = 0; c < 4; c++) o[nt][c] = 0.f;
    float mA = -1e30f, mB = -1e30f, lA = 0.f, lB = 0.f;

    for (int kt = 0; kt < ntiles; kt++) {
        const uint32_t kvb = sb + Q_SM_BYTES + (kt & 1) * KV_ST;
        if (kt + 1 < ntiles) {
            attn_load_kv(sb + Q_SM_BYTES + ((kt + 1) & 1) * KV_ST, ksrc0, vsrc0, kt + 1, tid);
            CP_COMMIT();
            CP_WAIT1();
        } else {
            CP_WAIT0();
        }
        __syncthreads();
        const uint32_t ksm = kvb;
        const uint32_t vsm = kvb + K_SM_BYTES;

        // ---- QK^T: 3-term split ----
        float s[8][4];
#pragma unroll
        for (int nt = 0; nt < 8; nt++)
#pragma unroll
            for (int c = 0; c < 4; c++) s[nt][c] = 0.f;

#pragma unroll
        for (int kst = 0; kst < 8; kst++) {
            uint32_t ah[4], al[4];
            ldmx4(ah[0], ah[1], ah[2], ah[3],
                  qsm + a_off + (((kst * 2 + a_k16) ^ a_x) << 4));
            ldmx4(al[0], al[1], al[2], al[3],
                  qsm + a_off + (((16 + kst * 2 + a_k16) ^ a_x) << 4));
#pragma unroll
            for (int np = 0; np < 4; np++) {
                uint32_t bh[4], bl[4];
                ldmx4(bh[0], bh[1], bh[2], bh[3],
                      ksm + kb_off[np] + (((kst * 2 + b_k16) ^ kb_x[np]) << 4));
                ldmx4(bl[0], bl[1], bl[2], bl[3],
                      ksm + kb_off[np] + (((16 + kst * 2 + b_k16) ^ kb_x[np]) << 4));
                mma_bf16(s[2*np],   ah, bh[0], bh[1]);
                mma_bf16(s[2*np+1], ah, bh[2], bh[3]);
                mma_bf16(s[2*np],   ah, bl[0], bl[1]);
                mma_bf16(s[2*np+1], ah, bl[2], bl[3]);
                mma_bf16(s[2*np],   al, bh[0], bh[1]);
                mma_bf16(s[2*np+1], al, bh[2], bh[3]);
            }
        }

        // ---- mask partial tile ----
        if (kt * 64 + 64 > seqlen) {
            const int kbase = kt * 64 + (lane & 3) * 2;
#pragma unroll
            for (int nt = 0; nt < 8; nt++)
#pragma unroll
                for (int c = 0; c < 4; c++) {
                    int gk = kbase + nt * 8 + (c & 1);
                    if (gk >= seqlen) s[nt][c] = -1e30f;
                }
        }

        // ---- online softmax ----
        float pmA = -1e30f, pmB = -1e30f;
#pragma unroll
        for (int nt = 0; nt < 8; nt++) {
            pmA = fmaxf(pmA, fmaxf(s[nt][0], s[nt][1]));
            pmB = fmaxf(pmB, fmaxf(s[nt][2], s[nt][3]));
        }
        pmA = fmaxf(pmA, __shfl_xor_sync(0xffffffffu, pmA, 1));
        pmA = fmaxf(pmA, __shfl_xor_sync(0xffffffffu, pmA, 2));
        pmB = fmaxf(pmB, __shfl_xor_sync(0xffffffffu, pmB, 1));
        pmB = fmaxf(pmB, __shfl_xor_sync(0xffffffffu, pmB, 2));

        const float mnA = fmaxf(mA, pmA), mnB = fmaxf(mB, pmB);
        const float fA = __expf(mA - mnA), fB = __expf(mB - mnB);
        float sumA = 0.f, sumB = 0.f;
#pragma unroll
        for (int nt = 0; nt < 8; nt++) {
            s[nt][0] = __expf(s[nt][0] - mnA); sumA += s[nt][0];
            s[nt][1] = __expf(s[nt][1] - mnA); sumA += s[nt][1];
            s[nt][2] = __expf(s[nt][2] - mnB); sumB += s[nt][2];
            s[nt][3] = __expf(s[nt][3] - mnB); sumB += s[nt][3];
        }
        sumA += __shfl_xor_sync(0xffffffffu, sumA, 1);
        sumA += __shfl_xor_sync(0xffffffffu, sumA, 2);
        sumB += __shfl_xor_sync(0xffffffffu, sumB, 1);
        sumB += __shfl_xor_sync(0xffffffffu, sumB, 2);

        mA = mnA; mB = mnB;
        lA = lA * fA + sumA;
        lB = lB * fB + sumB;

#pragma unroll
        for (int nt = 0; nt < 16; nt++) {
            o[nt][0] *= fA; o[nt][1] *= fA;
            o[nt][2] *= fB; o[nt][3] *= fB;
        }

        // ---- pack P into A-fragments (hi/lo) ----
        uint32_t aph[4][4], apl[4][4];
#pragma unroll
        for (int kk = 0; kk < 4; kk++) {
            split2(s[2*kk][0],   s[2*kk][1],   aph[kk][0], apl[kk][0]);
            split2(s[2*kk][2],   s[2*kk][3],   aph[kk][1], apl[kk][1]);
            split2(s[2*kk+1][0], s[2*kk+1][1], aph[kk][2], apl[kk][2]);
            split2(s[2*kk+1][2], s[2*kk+1][3], aph[kk][3], apl[kk][3]);
        }

        // ---- P.V: 3-term split ----
#pragma unroll
        for (int np = 0; np < 8; np++) {
#pragma unroll
            for (int kk = 0; kk < 4; kk++) {
                uint32_t bvh[4], bvl[4];
                ldmx4(bvh[0], bvh[1], bvh[2], bvh[3],
                      vsm + vb_off[np] + (((kk * 2 + b_k16) ^ vb_x[np]) << 4));
                ldmx4(bvl[0], bvl[1], bvl[2], bvl[3],
                      vsm + 128 * 128 + vb_off[np] + (((kk * 2 + b_k16) ^ vb_x[np]) << 4));
                mma_bf16(o[2*np],   aph[kk], bvh[0], bvh[1]);
                mma_bf16(o[2*np+1], aph[kk], bvh[2], bvh[3]);
                mma_bf16(o[2*np],   aph[kk], bvl[0], bvl[1]);
                mma_bf16(o[2*np+1], aph[kk], bvl[2], bvl[3]);
                mma_bf16(o[2*np],   apl[kk], bvh[0], bvh[1]);
                mma_bf16(o[2*np+1], apl[kk], bvh[2], bvh[3]);
            }
        }
        __syncthreads();
    }

    // epilogue
    const float iA = 1.f / lA, iB = 1.f / lB;
    const int row0 = qb * 128 + wid * 16 + (lane >> 2);
    const int col0 = h * 128 + (lane & 3) * 2;
#pragma unroll
    for (int nt = 0; nt < 16; nt++) {
        float2 vA = {o[nt][0] * iA, o[nt][1] * iA};
        float2 vB = {o[nt][2] * iB, o[nt][3] * iB};
        *(float2*)&O[(size_t)row0 * DIM + col0 + nt * 8]       = vA;
        *(float2*)&O[(size_t)(row0 + 8) * DIM + col0 + nt * 8] = vB;
    }
}

// ---------------- launch ----------------------------------------------------
extern "C" void kernel_launch(void* const* d_in, const int* in_sizes, int n_in,
                              void* d_out, int out_size)
{
    const float* x    = (const float*)d_in[0];
    const float* Wq   = (const float*)d_in[1];
    const float* bq   = (const float*)d_in[2];
    const float* Wk   = (const float*)d_in[3];
    const float* bk   = (const float*)d_in[4];
    const float* Wv   = (const float*)d_in[5];
    const float* bv   = (const float*)d_in[6];
    const float* Wo   = (const float*)d_in[7];
    const float* bo   = (const float*)d_in[8];
    const float* nqw  = (const float*)d_in[9];
    const float* nkw  = (const float*)d_in[10];
    const float* cosb = (const float*)d_in[11];
    const float* sinb = (const float*)d_in[12];
    const int*   seql = (const int*)d_in[13];
    float* out = (float*)d_out;

    float *q, *k, *v, *ao;
    __nv_bfloat16 *x3, *ao3, *w3, *qsb, *ksb, *vtb;
    cudaGetSymbolAddress((void**)&q,   g_q);
    cudaGetSymbolAddress((void**)&k,   g_k);
    cudaGetSymbolAddress((void**)&v,   g_v);
    cudaGetSymbolAddress((void**)&ao,  g_ao);
    cudaGetSymbolAddress((void**)&x3,  g_x3);
    cudaGetSymbolAddress((void**)&ao3, g_ao3);
    cudaGetSymbolAddress((void**)&w3,  g_w3);
    cudaGetSymbolAddress((void**)&qsb, g_qs);
    cudaGetSymbolAddress((void**)&ksb, g_ks);
    cudaGetSymbolAddress((void**)&vtb, g_vt);

    const int SMEM_G = GSTAGES * TILE_B * 2;
    cudaFuncSetAttribute(gemm_mma_kernel, cudaFuncAttributeMaxDynamicSharedMemorySize, SMEM_G);
    cudaFuncSetAttribute(attn_mma_kernel, cudaFuncAttributeMaxDynamicSharedMemorySize, ATTN_SMEM);

    const int nx = S_LEN * DIM, nw = DIM * DIM;
    cvt3_kernel<<<(nx + 255) / 256, 256>>>(x,  x3, nx, 0);
    cvt3_kernel<<<(nw + 255) / 256, 256>>>(Wq, w3 + 0 * (size_t)DIM * K3, nw, 1);
    cvt3_kernel<<<(nw + 255) / 256, 256>>>(Wk, w3 + 1 * (size_t)DIM * K3, nw, 1);
    cvt3_kernel<<<(nw + 255) / 256, 256>>>(Wv, w3 + 2 * (size_t)DIM * K3, nw, 1);
    cvt3_kernel<<<(nw + 255) / 256, 256>>>(Wo, w3 + 3 * (size_t)DIM * K3, nw, 1);

    dim3 gg(DIM / GBN, S_LEN / GBM);
    gemm_mma_kernel<<<gg, 256, SMEM_G>>>(x3, w3 + 0 * (size_t)DIM * K3, bq, q, DIM);
    gemm_mma_kernel<<<gg, 256, SMEM_G>>>(x3, w3 + 1 * (size_t)DIM * K3, bk, k, DIM);
    gemm_mma_kernel<<<gg, 256, SMEM_G>>>(x3, w3 + 2 * (size_t)DIM * K3, bv, v, DIM);

    const float qscale = 0.08838834764831845f;   // 1/sqrt(128)
    rms_rope_split_kernel<<<S_LEN, 256>>>(q, nqw, cosb, sinb, qsb, qscale);
    rms_rope_split_kernel<<<S_LEN, 256>>>(k, nkw, cosb, sinb, ksb, 1.0f);
    vsplit_t_kernel<<<dim3(S_LEN / 32, DIM / 32), 256>>>(v, vtb);

    attn_mma_kernel<<<dim3(S_LEN / 128, NH), 256, ATTN_SMEM>>>(qsb, ksb, vtb, ao, seql);

    cvt3_kernel<<<(nx + 255) / 256, 256>>>(ao, ao3, nx, 0);
    gemm_mma_kernel<<<gg, 256, SMEM_G>>>(ao3, w3 + 3 * (size_t)DIM * K3, bo, out, DIM);
}

// round 5
// speedup vs baseline: 7.9098x; 1.1457x over previous
#include <cuda_runtime.h>
#include <cuda_bf16.h>
#include <math.h>
#include <stdint.h>

#define S_LEN 3072
#define DIM   2048
#define NH    16
#define HD    128
#define K3    (3*DIM)   // 6144: [hi | hi | lo] x [hi | lo | hi]

// ---------------- scratch (device globals; no allocations allowed) ----------
__device__ __align__(16) float g_qkv[S_LEN * 3 * DIM];           // [s][q|k|v]
__device__ __align__(16) float g_bias3[3 * DIM];
__device__ __align__(16) __nv_bfloat16 g_x3 [S_LEN * K3];
__device__ __align__(16) __nv_bfloat16 g_ao3[S_LEN * K3];
__device__ __align__(16) __nv_bfloat16 g_w3 [4][DIM * K3];
__device__ __align__(16) __nv_bfloat16 g_qs [NH * S_LEN * 256];  // [h][s][hi128|lo128]
__device__ __align__(16) __nv_bfloat16 g_ks [NH * S_LEN * 256];
__device__ __align__(16) __nv_bfloat16 g_vt [NH * 256 * S_LEN];  // [h][d:hi,d+128:lo][s]

// ---------------- PTX helpers ----------------------------------------------
__device__ __forceinline__ uint32_t smem_u32(const void* p) {
    uint32_t a;
    asm("{ .reg .u64 t; cvta.to.shared.u64 t, %1; cvt.u32.u64 %0, t; }" : "=r"(a) : "l"(p));
    return a;
}
__device__ __forceinline__ void cp_async16(uint32_t saddr, const void* g) {
    asm volatile("cp.async.cg.shared.global [%0], [%1], 16;" :: "r"(saddr), "l"(g));
}
#define CP_COMMIT() asm volatile("cp.async.commit_group;" ::: "memory")
#define CP_WAIT1()  asm volatile("cp.async.wait_group 1;" ::: "memory")
#define CP_WAIT0()  asm volatile("cp.async.wait_group 0;" ::: "memory")

__device__ __forceinline__ void ldmx4(uint32_t& r0, uint32_t& r1, uint32_t& r2, uint32_t& r3,
                                      uint32_t addr) {
    asm volatile("ldmatrix.sync.aligned.m8n8.x4.shared.b16 {%0,%1,%2,%3}, [%4];"
                 : "=r"(r0), "=r"(r1), "=r"(r2), "=r"(r3) : "r"(addr));
}
__device__ __forceinline__ void mma_bf16(float* c, const uint32_t* a, uint32_t b0, uint32_t b1) {
    asm volatile("mma.sync.aligned.m16n8k16.row.col.f32.bf16.bf16.f32 "
                 "{%0,%1,%2,%3}, {%4,%5,%6,%7}, {%8,%9}, {%0,%1,%2,%3};"
                 : "+f"(c[0]), "+f"(c[1]), "+f"(c[2]), "+f"(c[3])
                 : "r"(a[0]), "r"(a[1]), "r"(a[2]), "r"(a[3]), "r"(b0), "r"(b1));
}
__device__ __forceinline__ void split2(float a, float b, uint32_t& hi, uint32_t& lo) {
    __nv_bfloat16 ha = __float2bfloat16(a), hb = __float2bfloat16(b);
    __nv_bfloat16 la = __float2bfloat16(a - __bfloat162float(ha));
    __nv_bfloat16 lb = __float2bfloat16(b - __bfloat162float(hb));
    __nv_bfloat162 H; H.x = ha; H.y = hb;
    __nv_bfloat162 L; L.x = la; L.y = lb;
    hi = *reinterpret_cast<uint32_t*>(&H);
    lo = *reinterpret_cast<uint32_t*>(&L);
}

// ---------------- split-bf16 conversion (GEMM inputs) -----------------------
__global__ __launch_bounds__(256)
void cvt3_kernel(const float* __restrict__ src, __nv_bfloat16* __restrict__ dst,
                 int nelem, int mode)
{
    int i = blockIdx.x * 256 + threadIdx.x;
    if (i >= nelem) return;
    float v = src[i];
    __nv_bfloat16 hi = __float2bfloat16(v);
    __nv_bfloat16 lo = __float2bfloat16(v - __bfloat162float(hi));
    int row = i >> 11;
    int c   = i & 2047;
    size_t base = (size_t)row * K3;
    if (mode == 0) {
        dst[base + c] = hi; dst[base + DIM + c] = hi; dst[base + 2*DIM + c] = lo;
    } else {
        dst[base + c] = hi; dst[base + DIM + c] = lo; dst[base + 2*DIM + c] = hi;
    }
}

__global__ __launch_bounds__(256)
void bias3_kernel(const float* __restrict__ bq, const float* __restrict__ bk,
                  const float* __restrict__ bv, float* __restrict__ dst)
{
    int i = blockIdx.x * 256 + threadIdx.x;
    if (i >= 3 * DIM) return;
    dst[i] = (i < DIM) ? bq[i] : (i < 2 * DIM ? bk[i - DIM] : bv[i - 2 * DIM]);
}

// ---------------- mma.sync GEMM: C[M,Nn] = A[M,K3] @ B[Nn,K3]^T + bias ------
// 3-stage cp.async pipeline, 96KB smem, 2 CTA/SM.
#define GBM 128
#define GBN 128
#define GBK 64
#define GSTAGES 3
#define GNITER (K3 / GBK)
#define TILE_B 16384
#define SMEM_G (GSTAGES * TILE_B * 2)   // 98304

__device__ __forceinline__ void g_load_stage(uint32_t sA, uint32_t sB,
    const __nv_bfloat16* __restrict__ A, const __nv_bfloat16* __restrict__ B,
    int bm, int bn, int kc, int tid)
{
#pragma unroll
    for (int i = 0; i < 4; i++) {
        int c = tid + i * 256;
        int row = c >> 3, cc = c & 7;
        cp_async16(sA + row * 128 + ((cc ^ (row & 7)) << 4),
                   A + (size_t)(bm + row) * K3 + kc + cc * 8);
    }
#pragma unroll
    for (int i = 0; i < 4; i++) {
        int c = tid + i * 256;
        int row = c >> 3, cc = c & 7;
        cp_async16(sB + row * 128 + ((cc ^ (row & 7)) << 4),
                   B + (size_t)(bn + row) * K3 + kc + cc * 8);
    }
}

__global__ __launch_bounds__(256, 2)
void gemm_mma_kernel(const __nv_bfloat16* __restrict__ A,
                     const __nv_bfloat16* __restrict__ B,
                     const float* __restrict__ bias, float* __restrict__ C, int Nn)
{
    extern __shared__ __align__(1024) char smem[];
    const uint32_t sb = smem_u32(smem);
    const uint32_t sAb = sb;
    const uint32_t sBb = sb + GSTAGES * TILE_B;

    const int tid = threadIdx.x;
    const int wid = tid >> 5, lane = tid & 31;
    const int bm = blockIdx.y * GBM, bn = blockIdx.x * GBN;
    const int wm = (wid & 1) * 64;
    const int wn = (wid >> 1) * 32;

    const int a_row = lane & 15;
    const int a_kh  = (lane >> 4);                       // 0/1 16B chunk
    const int b_row = (lane & 7) + ((lane >> 4) << 3);
    const int b_kh  = (lane >> 3) & 1;

    float acc[4][4][4];
#pragma unroll
    for (int mt = 0; mt < 4; mt++)
#pragma unroll
        for (int nt = 0; nt < 4; nt++)
#pragma unroll
            for (int r = 0; r < 4; r++) acc[mt][nt][r] = 0.f;

#pragma unroll
    for (int s = 0; s < GSTAGES - 1; s++) {
        g_load_stage(sAb + s * TILE_B, sBb + s * TILE_B, A, B, bm, bn, s * GBK, tid);
        CP_COMMIT();
    }

    uint32_t a_base[4], b_base[2]; int a_xm[4], b_xm[2];
#pragma unroll
    for (int mt = 0; mt < 4; mt++) {
        int row = wm + mt * 16 + a_row;
        a_base[mt] = row * 128;
        a_xm[mt] = row & 7;
    }
#pragma unroll
    for (int np = 0; np < 2; np++) {
        int row = wn + np * 16 + b_row;
        b_base[np] = row * 128;
        b_xm[np] = row & 7;
    }

    int cs = 0, ls = GSTAGES - 1;
    for (int it = 0; it < GNITER; it++) {
        CP_WAIT1();
        __syncthreads();
        const uint32_t sA = sAb + cs * TILE_B;
        const uint32_t sB = sBb + cs * TILE_B;

#pragma unroll
        for (int ks = 0; ks < 4; ks++) {
            uint32_t af[4][4];
#pragma unroll
            for (int mt = 0; mt < 4; mt++)
                ldmx4(af[mt][0], af[mt][1], af[mt][2], af[mt][3],
                      sA + a_base[mt] + (((ks * 2 + a_kh) ^ a_xm[mt]) << 4));
            uint32_t bfr[2][4];
#pragma unroll
            for (int np = 0; np < 2; np++)
                ldmx4(bfr[np][0], bfr[np][1], bfr[np][2], bfr[np][3],
                      sB + b_base[np] + (((ks * 2 + b_kh) ^ b_xm[np]) << 4));
#pragma unroll
            for (int mt = 0; mt < 4; mt++)
#pragma unroll
                for (int nt = 0; nt < 4; nt++)
                    mma_bf16(acc[mt][nt], af[mt],
                             bfr[nt >> 1][(nt & 1) * 2], bfr[nt >> 1][(nt & 1) * 2 + 1]);
        }

        const int li = it + GSTAGES - 1;
        if (li < GNITER)
            g_load_stage(sAb + ls * TILE_B, sBb + ls * TILE_B, A, B, bm, bn, li * GBK, tid);
        CP_COMMIT();
        cs = (cs + 1 == GSTAGES) ? 0 : cs + 1;
        ls = (ls + 1 == GSTAGES) ? 0 : ls + 1;
    }

    const int tq = lane >> 2, tr4 = lane & 3;
#pragma unroll
    for (int mt = 0; mt < 4; mt++) {
#pragma unroll
        for (int nt = 0; nt < 4; nt++) {
            const int row = bm + wm + mt * 16 + tq;
            const int col = bn + wn + nt * 8 + tr4 * 2;
            const float b0 = bias[col], b1 = bias[col + 1];
            float2 v0 = {acc[mt][nt][0] + b0, acc[mt][nt][1] + b1};
            float2 v1 = {acc[mt][nt][2] + b0, acc[mt][nt][3] + b1};
            *(float2*)&C[(size_t)row * Nn + col]       = v0;
            *(float2*)&C[(size_t)(row + 8) * Nn + col] = v1;
        }
    }
}

// ---------------- RMSNorm + RoPE + hi/lo split -> [NH][S][256] bf16 ---------
// src points at q (or k) column block inside g_qkv; row stride = 3*DIM.
__global__ __launch_bounds__(256)
void rms_rope_split_kernel(const float* __restrict__ src, const float* __restrict__ w,
                           const float* __restrict__ cosb, const float* __restrict__ sinb,
                           __nv_bfloat16* __restrict__ dst, float outscale)
{
    const int row = blockIdx.x;
    const float* p = src + (size_t)row * (3 * DIM);
    const int tid = threadIdx.x;

    float ss = 0.f;
    for (int i = tid; i < DIM; i += 256) { float v = p[i]; ss += v * v; }
#pragma unroll
    for (int off = 16; off > 0; off >>= 1) ss += __shfl_xor_sync(0xffffffffu, ss, off);

    __shared__ float red[8];
    __shared__ float sc;
    if ((tid & 31) == 0) red[tid >> 5] = ss;
    __syncthreads();
    if (tid == 0) {
        float t = 0.f;
#pragma unroll
        for (int i = 0; i < 8; i++) t += red[i];
        sc = rsqrtf(t / (float)DIM + 1e-6f);
    }
    __syncthreads();
    const float scale = sc;

    const float* crow = cosb + (size_t)row * HD;
    const float* srow = sinb + (size_t)row * HD;
    for (int pi = tid; pi < DIM / 2; pi += 256) {
        int i0 = 2 * pi;
        int h = i0 >> 7;
        int d = i0 & (HD - 1);
        float2 xv = *(const float2*)&p[i0];
        float e = xv.x * scale * w[i0];
        float o = xv.y * scale * w[i0 + 1];
        float c = crow[d], s = srow[d];
        float rx = (e * c - o * s) * outscale;
        float ry = (o * c + e * s) * outscale;
        uint32_t hi, lo;
        split2(rx, ry, hi, lo);
        __nv_bfloat16* base = dst + (size_t)h * S_LEN * 256 + (size_t)row * 256;
        *(uint32_t*)&base[d]       = hi;
        *(uint32_t*)&base[128 + d] = lo;
    }
}

// ---------------- V transpose + split -> [NH][256][S] bf16 ------------------
__global__ __launch_bounds__(256)
void vsplit_t_kernel(const float* __restrict__ qkv, __nv_bfloat16* __restrict__ vt)
{
    __shared__ float tile[32][33];
    const int s0 = blockIdx.x * 32;
    const int c0 = blockIdx.y * 32;
    const int tx = threadIdx.x & 31;
    const int ty = threadIdx.x >> 5;

#pragma unroll
    for (int i = 0; i < 4; i++) {
        int r = ty + i * 8;
        tile[r][tx] = qkv[(size_t)(s0 + r) * (3 * DIM) + 2 * DIM + c0 + tx];
    }
    __syncthreads();
#pragma unroll
    for (int i = 0; i < 4; i++) {
        int dr = ty + i * 8;
        int dg = c0 + dr;
        int h = dg >> 7, d = dg & 127;
        float val = tile[tx][dr];
        __nv_bfloat16 hi = __float2bfloat16(val);
        __nv_bfloat16 lo = __float2bfloat16(val - __bfloat162float(hi));
        size_t base = (size_t)h * 256 * S_LEN;
        vt[base + (size_t)d * S_LEN + s0 + tx]         = hi;
        vt[base + (size_t)(d + 128) * S_LEN + s0 + tx] = lo;
    }
}

// ---------------- tensor-core flash attention (writes split ao3) ------------
#define Q_SM_BYTES  (128 * 512)
#define K_SM_BYTES  (64 * 512)
#define V_SM_BYTES  (256 * 128)
#define KV_ST       (K_SM_BYTES + V_SM_BYTES)
#define ATTN_SMEM   (Q_SM_BYTES + 2 * KV_ST)

#define ACP_WAIT1() asm volatile("cp.async.wait_group 1;" ::: "memory")
#define ACP_WAIT0() asm volatile("cp.async.wait_group 0;" ::: "memory")

__device__ __forceinline__ void attn_load_kv(uint32_t kvb,
    const __nv_bfloat16* __restrict__ ksrc0, const __nv_bfloat16* __restrict__ vsrc0,
    int kt, int tid)
{
    const __nv_bfloat16* ksrc = ksrc0 + (size_t)kt * 64 * 256;
#pragma unroll
    for (int u = 0; u < 8; u++) {
        int c = tid + u * 256;
        int r = c >> 5, ch = c & 31;
        cp_async16(kvb + r * 512 + ((ch ^ (r & 7)) << 4), ksrc + (size_t)r * 256 + ch * 8);
    }
    const __nv_bfloat16* vsrc = vsrc0 + kt * 64;
    const uint32_t vb = kvb + K_SM_BYTES;
#pragma unroll
    for (int u = 0; u < 8; u++) {
        int c = tid + u * 256;
        int r = c >> 3, ch = c & 7;
        cp_async16(vb + r * 128 + ((ch ^ (r & 7)) << 4), vsrc + (size_t)r * S_LEN + ch * 8);
    }
}

__global__ __launch_bounds__(256, 1)
void attn_mma_kernel(const __nv_bfloat16* __restrict__ qs,
                     const __nv_bfloat16* __restrict__ ks,
                     const __nv_bfloat16* __restrict__ vt,
                     __nv_bfloat16* __restrict__ ao3, const int* __restrict__ seq_lens)
{
    extern __shared__ __align__(1024) char smem[];
    const uint32_t sb = smem_u32(smem);
    const uint32_t qsm = sb;
    const int tid = threadIdx.x, lane = tid & 31, wid = tid >> 5;
    const int qb = blockIdx.x, h = blockIdx.y;

    const int seqlen = seq_lens[0];
    const int ntiles = (seqlen + 63) >> 6;

    const __nv_bfloat16* qsrc  = qs + ((size_t)h * S_LEN + qb * 128) * 256;
    const __nv_bfloat16* ksrc0 = ks + (size_t)h * S_LEN * 256;
    const __nv_bfloat16* vsrc0 = vt + (size_t)h * 256 * S_LEN;

#pragma unroll
    for (int u = 0; u < 16; u++) {
        int c = tid + u * 256;
        int r = c >> 5, ch = c & 31;
        cp_async16(qsm + r * 512 + ((ch ^ (r & 7)) << 4), qsrc + (size_t)r * 256 + ch * 8);
    }
    attn_load_kv(sb + Q_SM_BYTES, ksrc0, vsrc0, 0, tid);
    CP_COMMIT();

    const int a_row = wid * 16 + (lane & 15);
    const uint32_t a_off = a_row * 512;
    const int a_x = a_row & 7;
    const int a_k16 = lane >> 4;
    const int b_row = (lane & 7) + ((lane >> 4) << 3);
    const int b_k16 = (lane >> 3) & 1;

    uint32_t kb_off[4]; int kb_x[4];
#pragma unroll
    for (int np = 0; np < 4; np++) {
        int row = np * 16 + b_row;
        kb_off[np] = row * 512; kb_x[np] = row & 7;
    }
    uint32_t vb_off[8]; int vb_x[8];
#pragma unroll
    for (int np = 0; np < 8; np++) {
        int row = np * 16 + b_row;
        vb_off[np] = row * 128; vb_x[np] = row & 7;
    }

    float o[16][4];
#pragma unroll
    for (int nt = 0; nt < 16; nt++)
#pragma unroll
        for (int c = 0; c < 4; c++) o[nt][c] = 0.f;
    float mA = -1e30f, mB = -1e30f, lA = 0.f, lB = 0.f;

    for (int kt = 0; kt < ntiles; kt++) {
        const uint32_t kvb = sb + Q_SM_BYTES + (kt & 1) * KV_ST;
        if (kt + 1 < ntiles) {
            attn_load_kv(sb + Q_SM_BYTES + ((kt + 1) & 1) * KV_ST, ksrc0, vsrc0, kt + 1, tid);
            CP_COMMIT();
            ACP_WAIT1();
        } else {
            ACP_WAIT0();
        }
        __syncthreads();
        const uint32_t ksm = kvb;
        const uint32_t vsm = kvb + K_SM_BYTES;

        float s[8][4];
#pragma unroll
        for (int nt = 0; nt < 8; nt++)
#pragma unroll
            for (int c = 0; c < 4; c++) s[nt][c] = 0.f;

#pragma unroll
        for (int kst = 0; kst < 8; kst++) {
            uint32_t ah[4], al[4];
            ldmx4(ah[0], ah[1], ah[2], ah[3],
                  qsm + a_off + (((kst * 2 + a_k16) ^ a_x) << 4));
            ldmx4(al[0], al[1], al[2], al[3],
                  qsm + a_off + (((16 + kst * 2 + a_k16) ^ a_x) << 4));
#pragma unroll
            for (int np = 0; np < 4; np++) {
                uint32_t bh[4], bl[4];
                ldmx4(bh[0], bh[1], bh[2], bh[3],
                      ksm + kb_off[np] + (((kst * 2 + b_k16) ^ kb_x[np]) << 4));
                ldmx4(bl[0], bl[1], bl[2], bl[3],
                      ksm + kb_off[np] + (((16 + kst * 2 + b_k16) ^ kb_x[np]) << 4));
                mma_bf16(s[2*np],   ah, bh[0], bh[1]);
                mma_bf16(s[2*np+1], ah, bh[2], bh[3]);
                mma_bf16(s[2*np],   ah, bl[0], bl[1]);
                mma_bf16(s[2*np+1], ah, bl[2], bl[3]);
                mma_bf16(s[2*np],   al, bh[0], bh[1]);
                mma_bf16(s[2*np+1], al, bh[2], bh[3]);
            }
        }

        if (kt * 64 + 64 > seqlen) {
            const int kbase = kt * 64 + (lane & 3) * 2;
#pragma unroll
            for (int nt = 0; nt < 8; nt++)
#pragma unroll
                for (int c = 0; c < 4; c++) {
                    int gk = kbase + nt * 8 + (c & 1);
                    if (gk >= seqlen) s[nt][c] = -1e30f;
                }
        }

        float pmA = -1e30f, pmB = -1e30f;
#pragma unroll
        for (int nt = 0; nt < 8; nt++) {
            pmA = fmaxf(pmA, fmaxf(s[nt][0], s[nt][1]));
            pmB = fmaxf(pmB, fmaxf(s[nt][2], s[nt][3]));
        }
        pmA = fmaxf(pmA, __shfl_xor_sync(0xffffffffu, pmA, 1));
        pmA = fmaxf(pmA, __shfl_xor_sync(0xffffffffu, pmA, 2));
        pmB = fmaxf(pmB, __shfl_xor_sync(0xffffffffu, pmB, 1));
        pmB = fmaxf(pmB, __shfl_xor_sync(0xffffffffu, pmB, 2));

        const float mnA = fmaxf(mA, pmA), mnB = fmaxf(mB, pmB);
        const float fA = __expf(mA - mnA), fB = __expf(mB - mnB);
        float sumA = 0.f, sumB = 0.f;
#pragma unroll
        for (int nt = 0; nt < 8; nt++) {
            s[nt][0] = __expf(s[nt][0] - mnA); sumA += s[nt][0];
            s[nt][1] = __expf(s[nt][1] - mnA); sumA += s[nt][1];
            s[nt][2] = __expf(s[nt][2] - mnB); sumB += s[nt][2];
            s[nt][3] = __expf(s[nt][3] - mnB); sumB += s[nt][3];
        }
        sumA += __shfl_xor_sync(0xffffffffu, sumA, 1);
        sumA += __shfl_xor_sync(0xffffffffu, sumA, 2);
        sumB += __shfl_xor_sync(0xffffffffu, sumB, 1);
        sumB += __shfl_xor_sync(0xffffffffu, sumB, 2);

        mA = mnA; mB = mnB;
        lA = lA * fA + sumA;
        lB = lB * fB + sumB;

#pragma unroll
        for (int nt = 0; nt < 16; nt++) {
            o[nt][0] *= fA; o[nt][1] *= fA;
            o[nt][2] *= fB; o[nt][3] *= fB;
        }

        uint32_t aph[4][4], apl[4][4];
#pragma unroll
        for (int kk = 0; kk < 4; kk++) {
            split2(s[2*kk][0],   s[2*kk][1],   aph[kk][0], apl[kk][0]);
            split2(s[2*kk][2],   s[2*kk][3],   aph[kk][1], apl[kk][1]);
            split2(s[2*kk+1][0], s[2*kk+1][1], aph[kk][2], apl[kk][2]);
            split2(s[2*kk+1][2], s[2*kk+1][3], aph[kk][3], apl[kk][3]);
        }

#pragma unroll
        for (int np = 0; np < 8; np++) {
#pragma unroll
            for (int kk = 0; kk < 4; kk++) {
                uint32_t bvh[4], bvl[4];
                ldmx4(bvh[0], bvh[1], bvh[2], bvh[3],
                      vsm + vb_off[np] + (((kk * 2 + b_k16) ^ vb_x[np]) << 4));
                ldmx4(bvl[0], bvl[1], bvl[2], bvl[3],
                      vsm + 128 * 128 + vb_off[np] + (((kk * 2 + b_k16) ^ vb_x[np]) << 4));
                mma_bf16(o[2*np],   aph[kk], bvh[0], bvh[1]);
                mma_bf16(o[2*np+1], aph[kk], bvh[2], bvh[3]);
                mma_bf16(o[2*np],   aph[kk], bvl[0], bvl[1]);
                mma_bf16(o[2*np+1], aph[kk], bvl[2], bvl[3]);
                mma_bf16(o[2*np],   apl[kk], bvh[0], bvh[1]);
                mma_bf16(o[2*np+1], apl[kk], bvh[2], bvh[3]);
            }
        }
        __syncthreads();
    }

    // epilogue: write hi/hi/lo split directly into ao3 [S][K3]
    const float iA = 1.f / lA, iB = 1.f / lB;
    const int row0 = qb * 128 + wid * 16 + (lane >> 2);
    const int col0 = h * 128 + (lane & 3) * 2;
#pragma unroll
    for (int nt = 0; nt < 16; nt++) {
        float xA = o[nt][0] * iA, yA = o[nt][1] * iA;
        float xB = o[nt][2] * iB, yB = o[nt][3] * iB;
        uint32_t hA, loA, hB, loB;
        split2(xA, yA, hA, loA);
        split2(xB, yB, hB, loB);
        __nv_bfloat16* pA = ao3 + (size_t)row0 * K3 + col0 + nt * 8;
        __nv_bfloat16* pB = ao3 + (size_t)(row0 + 8) * K3 + col0 + nt * 8;
        *(uint32_t*)&pA[0]        = hA;
        *(uint32_t*)&pA[DIM]      = hA;
        *(uint32_t*)&pA[2 * DIM]  = loA;
        *(uint32_t*)&pB[0]        = hB;
        *(uint32_t*)&pB[DIM]      = hB;
        *(uint32_t*)&pB[2 * DIM]  = loB;
    }
}

// ---------------- launch ----------------------------------------------------
extern "C" void kernel_launch(void* const* d_in, const int* in_sizes, int n_in,
                              void* d_out, int out_size)
{
    const float* x    = (const float*)d_in[0];
    const float* Wq   = (const float*)d_in[1];
    const float* bq   = (const float*)d_in[2];
    const float* Wk   = (const float*)d_in[3];
    const float* bk   = (const float*)d_in[4];
    const float* Wv   = (const float*)d_in[5];
    const float* bv   = (const float*)d_in[6];
    const float* Wo   = (const float*)d_in[7];
    const float* bo   = (const float*)d_in[8];
    const float* nqw  = (const float*)d_in[9];
    const float* nkw  = (const float*)d_in[10];
    const float* cosb = (const float*)d_in[11];
    const float* sinb = (const float*)d_in[12];
    const int*   seql = (const int*)d_in[13];
    float* out = (float*)d_out;

    float *qkv, *bias3;
    __nv_bfloat16 *x3, *ao3, *w3, *qsb, *ksb, *vtb;
    cudaGetSymbolAddress((void**)&qkv,   g_qkv);
    cudaGetSymbolAddress((void**)&bias3, g_bias3);
    cudaGetSymbolAddress((void**)&x3,    g_x3);
    cudaGetSymbolAddress((void**)&ao3,   g_ao3);
    cudaGetSymbolAddress((void**)&w3,    g_w3);
    cudaGetSymbolAddress((void**)&qsb,   g_qs);
    cudaGetSymbolAddress((void**)&ksb,   g_ks);
    cudaGetSymbolAddress((void**)&vtb,   g_vt);

    cudaFuncSetAttribute(gemm_mma_kernel, cudaFuncAttributeMaxDynamicSharedMemorySize, SMEM_G);
    cudaFuncSetAttribute(attn_mma_kernel, cudaFuncAttributeMaxDynamicSharedMemorySize, ATTN_SMEM);

    const int nx = S_LEN * DIM, nw = DIM * DIM;
    cvt3_kernel<<<(nx + 255) / 256, 256>>>(x,  x3, nx, 0);
    cvt3_kernel<<<(nw + 255) / 256, 256>>>(Wq, w3 + 0 * (size_t)DIM * K3, nw, 1);
    cvt3_kernel<<<(nw + 255) / 256, 256>>>(Wk, w3 + 1 * (size_t)DIM * K3, nw, 1);
    cvt3_kernel<<<(nw + 255) / 256, 256>>>(Wv, w3 + 2 * (size_t)DIM * K3, nw, 1);
    cvt3_kernel<<<(nw + 255) / 256, 256>>>(Wo, w3 + 3 * (size_t)DIM * K3, nw, 1);
    bias3_kernel<<<(3 * DIM + 255) / 256, 256>>>(bq, bk, bv, bias3);

    // fused QKV projection: B rows 0..6143 span Wq|Wk|Wv (contiguous in g_w3)
    gemm_mma_kernel<<<dim3(3 * DIM / GBN, S_LEN / GBM), 256, SMEM_G>>>(
        x3, w3, bias3, qkv, 3 * DIM);

    const float qscale = 0.08838834764831845f;   // 1/sqrt(128)
    rms_rope_split_kernel<<<S_LEN, 256>>>(qkv,        nqw, cosb, sinb, qsb, qscale);
    rms_rope_split_kernel<<<S_LEN, 256>>>(qkv + DIM,  nkw, cosb, sinb, ksb, 1.0f);
    vsplit_t_kernel<<<dim3(S_LEN / 32, DIM / 32), 256>>>(qkv, vtb);

    attn_mma_kernel<<<dim3(S_LEN / 128, NH), 256, ATTN_SMEM>>>(qsb, ksb, vtb, ao3, seql);

    gemm_mma_kernel<<<dim3(DIM / GBN, S_LEN / GBM), 256, SMEM_G>>>(
        ao3, w3 + 3 * (size_t)DIM * K3, bo, out, DIM);
}

// round 6
// speedup vs baseline: 8.0330x; 1.0156x over previous
#include <cuda_runtime.h>
#include <cuda_bf16.h>
#include <math.h>
#include <stdint.h>

#define S_LEN 3072
#define DIM   2048
#define NH    16
#define HD    128
#define K3    (3*DIM)   // 6144: [hi | hi | lo] x [hi | lo | hi]

// ---------------- scratch (device globals; no allocations allowed) ----------
__device__ __align__(16) float g_qkv[S_LEN * 3 * DIM];           // [s][q|k|v]
__device__ __align__(16) float g_bias3[3 * DIM];
__device__ __align__(16) __nv_bfloat16 g_x3 [S_LEN * K3];
__device__ __align__(16) __nv_bfloat16 g_ao3[S_LEN * K3];
__device__ __align__(16) __nv_bfloat16 g_w3 [4][DIM * K3];
__device__ __align__(16) __nv_bfloat16 g_qs [NH * S_LEN * 256];  // [h][s][hi128|lo128]
__device__ __align__(16) __nv_bfloat16 g_ks [NH * S_LEN * 256];
__device__ __align__(16) __nv_bfloat16 g_vt [NH * 256 * S_LEN];  // [h][d:hi,d+128:lo][s]

// ---------------- PTX helpers ----------------------------------------------
__device__ __forceinline__ uint32_t smem_u32(const void* p) {
    uint32_t a;
    asm("{ .reg .u64 t; cvta.to.shared.u64 t, %1; cvt.u32.u64 %0, t; }" : "=r"(a) : "l"(p));
    return a;
}
__device__ __forceinline__ void cp_async16(uint32_t saddr, const void* g) {
    asm volatile("cp.async.cg.shared.global [%0], [%1], 16;" :: "r"(saddr), "l"(g));
}
#define CP_COMMIT() asm volatile("cp.async.commit_group;" ::: "memory")
#define CP_WAIT2()  asm volatile("cp.async.wait_group 2;" ::: "memory")
#define CP_WAIT1()  asm volatile("cp.async.wait_group 1;" ::: "memory")
#define CP_WAIT0()  asm volatile("cp.async.wait_group 0;" ::: "memory")

__device__ __forceinline__ void ldmx4(uint32_t& r0, uint32_t& r1, uint32_t& r2, uint32_t& r3,
                                      uint32_t addr) {
    asm volatile("ldmatrix.sync.aligned.m8n8.x4.shared.b16 {%0,%1,%2,%3}, [%4];"
                 : "=r"(r0), "=r"(r1), "=r"(r2), "=r"(r3) : "r"(addr));
}
__device__ __forceinline__ void mma_bf16(float* c, const uint32_t* a, uint32_t b0, uint32_t b1) {
    asm volatile("mma.sync.aligned.m16n8k16.row.col.f32.bf16.bf16.f32 "
                 "{%0,%1,%2,%3}, {%4,%5,%6,%7}, {%8,%9}, {%0,%1,%2,%3};"
                 : "+f"(c[0]), "+f"(c[1]), "+f"(c[2]), "+f"(c[3])
                 : "r"(a[0]), "r"(a[1]), "r"(a[2]), "r"(a[3]), "r"(b0), "r"(b1));
}
__device__ __forceinline__ void split2(float a, float b, uint32_t& hi, uint32_t& lo) {
    __nv_bfloat16 ha = __float2bfloat16(a), hb = __float2bfloat16(b);
    __nv_bfloat16 la = __float2bfloat16(a - __bfloat162float(ha));
    __nv_bfloat16 lb = __float2bfloat16(b - __bfloat162float(hb));
    __nv_bfloat162 H; H.x = ha; H.y = hb;
    __nv_bfloat162 L; L.x = la; L.y = lb;
    hi = *reinterpret_cast<uint32_t*>(&H);
    lo = *reinterpret_cast<uint32_t*>(&L);
}

// ---------------- split-bf16 conversion, vectorized (4B stores) -------------
// mode 0 (activation): [hi | hi | lo]   mode 1 (weight): [hi | lo | hi]
__global__ __launch_bounds__(256)
void cvt3v_kernel(const float* __restrict__ src, __nv_bfloat16* __restrict__ dst,
                  int npairs, int mode)
{
    int p = blockIdx.x * 256 + threadIdx.x;
    if (p >= npairs) return;
    int i = p * 2;
    float2 v = *(const float2*)&src[i];
    uint32_t hi, lo;
    split2(v.x, v.y, hi, lo);
    int row = i >> 11;
    int c   = i & 2047;
    __nv_bfloat16* base = dst + (size_t)row * K3 + c;
    if (mode == 0) {
        *(uint32_t*)&base[0]       = hi;
        *(uint32_t*)&base[DIM]     = hi;
        *(uint32_t*)&base[2 * DIM] = lo;
    } else {
        *(uint32_t*)&base[0]       = hi;
        *(uint32_t*)&base[DIM]     = lo;
        *(uint32_t*)&base[2 * DIM] = hi;
    }
}

__global__ __launch_bounds__(256)
void bias3_kernel(const float* __restrict__ bq, const float* __restrict__ bk,
                  const float* __restrict__ bv, float* __restrict__ dst)
{
    int i = blockIdx.x * 256 + threadIdx.x;
    if (i >= 3 * DIM) return;
    dst[i] = (i < DIM) ? bq[i] : (i < 2 * DIM ? bk[i - DIM] : bv[i - 2 * DIM]);
}

// ---------------- mma.sync GEMM: C[M,Nn] = A[M,K3] @ B[Nn,K3]^T + bias ------
#define GBM 128
#define GBN 128
#define GBK 64
#define GSTAGES 3
#define GNITER (K3 / GBK)
#define TILE_B 16384
#define SMEM_G (GSTAGES * TILE_B * 2)   // 98304

__device__ __forceinline__ void g_load_stage(uint32_t sA, uint32_t sB,
    const __nv_bfloat16* __restrict__ A, const __nv_bfloat16* __restrict__ B,
    int bm, int bn, int kc, int tid)
{
#pragma unroll
    for (int i = 0; i < 4; i++) {
        int c = tid + i * 256;
        int row = c >> 3, cc = c & 7;
        cp_async16(sA + row * 128 + ((cc ^ (row & 7)) << 4),
                   A + (size_t)(bm + row) * K3 + kc + cc * 8);
    }
#pragma unroll
    for (int i = 0; i < 4; i++) {
        int c = tid + i * 256;
        int row = c >> 3, cc = c & 7;
        cp_async16(sB + row * 128 + ((cc ^ (row & 7)) << 4),
                   B + (size_t)(bn + row) * K3 + kc + cc * 8);
    }
}

__global__ __launch_bounds__(256, 2)
void gemm_mma_kernel(const __nv_bfloat16* __restrict__ A,
                     const __nv_bfloat16* __restrict__ B,
                     const float* __restrict__ bias, float* __restrict__ C, int Nn)
{
    extern __shared__ __align__(1024) char smem[];
    const uint32_t sb = smem_u32(smem);
    const uint32_t sAb = sb;
    const uint32_t sBb = sb + GSTAGES * TILE_B;

    const int tid = threadIdx.x;
    const int wid = tid >> 5, lane = tid & 31;
    const int bm = blockIdx.y * GBM, bn = blockIdx.x * GBN;
    const int wm = (wid & 1) * 64;
    const int wn = (wid >> 1) * 32;

    const int a_row = lane & 15;
    const int a_kh  = (lane >> 4);
    const int b_row = (lane & 7) + ((lane >> 4) << 3);
    const int b_kh  = (lane >> 3) & 1;

    float acc[4][4][4];
#pragma unroll
    for (int mt = 0; mt < 4; mt++)
#pragma unroll
        for (int nt = 0; nt < 4; nt++)
#pragma unroll
            for (int r = 0; r < 4; r++) acc[mt][nt][r] = 0.f;

#pragma unroll
    for (int s = 0; s < GSTAGES - 1; s++) {
        g_load_stage(sAb + s * TILE_B, sBb + s * TILE_B, A, B, bm, bn, s * GBK, tid);
        CP_COMMIT();
    }

    uint32_t a_base[4], b_base[2]; int a_xm[4], b_xm[2];
#pragma unroll
    for (int mt = 0; mt < 4; mt++) {
        int row = wm + mt * 16 + a_row;
        a_base[mt] = row * 128;
        a_xm[mt] = row & 7;
    }
#pragma unroll
    for (int np = 0; np < 2; np++) {
        int row = wn + np * 16 + b_row;
        b_base[np] = row * 128;
        b_xm[np] = row & 7;
    }

    int cs = 0, ls = GSTAGES - 1;
    for (int it = 0; it < GNITER; it++) {
        CP_WAIT1();
        __syncthreads();
        const uint32_t sA = sAb + cs * TILE_B;
        const uint32_t sB = sBb + cs * TILE_B;

#pragma unroll
        for (int ks = 0; ks < 4; ks++) {
            uint32_t af[4][4];
#pragma unroll
            for (int mt = 0; mt < 4; mt++)
                ldmx4(af[mt][0], af[mt][1], af[mt][2], af[mt][3],
                      sA + a_base[mt] + (((ks * 2 + a_kh) ^ a_xm[mt]) << 4));
            uint32_t bfr[2][4];
#pragma unroll
            for (int np = 0; np < 2; np++)
                ldmx4(bfr[np][0], bfr[np][1], bfr[np][2], bfr[np][3],
                      sB + b_base[np] + (((ks * 2 + b_kh) ^ b_xm[np]) << 4));
#pragma unroll
            for (int mt = 0; mt < 4; mt++)
#pragma unroll
                for (int nt = 0; nt < 4; nt++)
                    mma_bf16(acc[mt][nt], af[mt],
                             bfr[nt >> 1][(nt & 1) * 2], bfr[nt >> 1][(nt & 1) * 2 + 1]);
        }

        const int li = it + GSTAGES - 1;
        if (li < GNITER)
            g_load_stage(sAb + ls * TILE_B, sBb + ls * TILE_B, A, B, bm, bn, li * GBK, tid);
        CP_COMMIT();
        cs = (cs + 1 == GSTAGES) ? 0 : cs + 1;
        ls = (ls + 1 == GSTAGES) ? 0 : ls + 1;
    }

    const int tq = lane >> 2, tr4 = lane & 3;
#pragma unroll
    for (int mt = 0; mt < 4; mt++) {
#pragma unroll
        for (int nt = 0; nt < 4; nt++) {
            const int row = bm + wm + mt * 16 + tq;
            const int col = bn + wn + nt * 8 + tr4 * 2;
            const float b0 = bias[col], b1 = bias[col + 1];
            float2 v0 = {acc[mt][nt][0] + b0, acc[mt][nt][1] + b1};
            float2 v1 = {acc[mt][nt][2] + b0, acc[mt][nt][3] + b1};
            *(float2*)&C[(size_t)row * Nn + col]       = v0;
            *(float2*)&C[(size_t)(row + 8) * Nn + col] = v1;
        }
    }
}

// ---------------- RMSNorm + RoPE + hi/lo split -> [NH][S][256] bf16 ---------
__global__ __launch_bounds__(256)
void rms_rope_split_kernel(const float* __restrict__ src, const float* __restrict__ w,
                           const float* __restrict__ cosb, const float* __restrict__ sinb,
                           __nv_bfloat16* __restrict__ dst, float outscale)
{
    const int row = blockIdx.x;
    const float* p = src + (size_t)row * (3 * DIM);
    const int tid = threadIdx.x;

    float ss = 0.f;
    for (int i = tid; i < DIM; i += 256) { float v = p[i]; ss += v * v; }
#pragma unroll
    for (int off = 16; off > 0; off >>= 1) ss += __shfl_xor_sync(0xffffffffu, ss, off);

    __shared__ float red[8];
    __shared__ float sc;
    if ((tid & 31) == 0) red[tid >> 5] = ss;
    __syncthreads();
    if (tid == 0) {
        float t = 0.f;
#pragma unroll
        for (int i = 0; i < 8; i++) t += red[i];
        sc = rsqrtf(t / (float)DIM + 1e-6f);
    }
    __syncthreads();
    const float scale = sc;

    const float* crow = cosb + (size_t)row * HD;
    const float* srow = sinb + (size_t)row * HD;
    for (int pi = tid; pi < DIM / 2; pi += 256) {
        int i0 = 2 * pi;
        int h = i0 >> 7;
        int d = i0 & (HD - 1);
        float2 xv = *(const float2*)&p[i0];
        float e = xv.x * scale * w[i0];
        float o = xv.y * scale * w[i0 + 1];
        float c = crow[d], s = srow[d];
        float rx = (e * c - o * s) * outscale;
        float ry = (o * c + e * s) * outscale;
        uint32_t hi, lo;
        split2(rx, ry, hi, lo);
        __nv_bfloat16* base = dst + (size_t)h * S_LEN * 256 + (size_t)row * 256;
        *(uint32_t*)&base[d]       = hi;
        *(uint32_t*)&base[128 + d] = lo;
    }
}

// ---------------- V transpose + split -> [NH][256][S] bf16 ------------------
__global__ __launch_bounds__(256)
void vsplit_t_kernel(const float* __restrict__ qkv, __nv_bfloat16* __restrict__ vt)
{
    __shared__ float tile[32][33];
    const int s0 = blockIdx.x * 32;
    const int c0 = blockIdx.y * 32;
    const int tx = threadIdx.x & 31;
    const int ty = threadIdx.x >> 5;

#pragma unroll
    for (int i = 0; i < 4; i++) {
        int r = ty + i * 8;
        tile[r][tx] = qkv[(size_t)(s0 + r) * (3 * DIM) + 2 * DIM + c0 + tx];
    }
    __syncthreads();
#pragma unroll
    for (int i = 0; i < 4; i++) {
        int dr = ty + i * 8;
        int dg = c0 + dr;
        int h = dg >> 7, d = dg & 127;
        float val = tile[tx][dr];
        __nv_bfloat16 hi = __float2bfloat16(val);
        __nv_bfloat16 lo = __float2bfloat16(val - __bfloat162float(hi));
        size_t base = (size_t)h * 256 * S_LEN;
        vt[base + (size_t)d * S_LEN + s0 + tx]         = hi;
        vt[base + (size_t)(d + 128) * S_LEN + s0 + tx] = lo;
    }
}

// ---------------- tensor-core flash attention -------------------------------
// Q in registers (extracted once), 3-stage KV cp.async pipeline.
#define K_SM_BYTES  (64 * 512)      // 32 KB
#define V_SM_BYTES  (256 * 128)     // 32 KB
#define KV_ST       (K_SM_BYTES + V_SM_BYTES)   // 64 KB
#define ATTN_SMEM   (3 * KV_ST)                  // 192 KB; Q uses stage-2 region in prologue

__device__ __forceinline__ void attn_load_kv(uint32_t kvb,
    const __nv_bfloat16* __restrict__ ksrc0, const __nv_bfloat16* __restrict__ vsrc0,
    int kt, int tid)
{
    const __nv_bfloat16* ksrc = ksrc0 + (size_t)kt * 64 * 256;
#pragma unroll
    for (int u = 0; u < 8; u++) {
        int c = tid + u * 256;
        int r = c >> 5, ch = c & 31;
        cp_async16(kvb + r * 512 + ((ch ^ (r & 7)) << 4), ksrc + (size_t)r * 256 + ch * 8);
    }
    const __nv_bfloat16* vsrc = vsrc0 + kt * 64;
    const uint32_t vb = kvb + K_SM_BYTES;
#pragma unroll
    for (int u = 0; u < 8; u++) {
        int c = tid + u * 256;
        int r = c >> 3, ch = c & 7;
        cp_async16(vb + r * 128 + ((ch ^ (r & 7)) << 4), vsrc + (size_t)r * S_LEN + ch * 8);
    }
}

__global__ __launch_bounds__(256, 1)
void attn_mma_kernel(const __nv_bfloat16* __restrict__ qs,
                     const __nv_bfloat16* __restrict__ ks,
                     const __nv_bfloat16* __restrict__ vt,
                     __nv_bfloat16* __restrict__ ao3, const int* __restrict__ seq_lens)
{
    extern __shared__ __align__(1024) char smem[];
    const uint32_t sb = smem_u32(smem);
    const int tid = threadIdx.x, lane = tid & 31, wid = tid >> 5;
    const int qb = blockIdx.x, h = blockIdx.y;

    const int seqlen = seq_lens[0];
    const int ntiles = (seqlen + 63) >> 6;

    const __nv_bfloat16* qsrc  = qs + ((size_t)h * S_LEN + qb * 128) * 256;
    const __nv_bfloat16* ksrc0 = ks + (size_t)h * S_LEN * 256;
    const __nv_bfloat16* vsrc0 = vt + (size_t)h * 256 * S_LEN;

    // prologue: Q into stage-2 region, kv(0) into stage 0
    const uint32_t qtmp = sb + 2 * KV_ST;
#pragma unroll
    for (int u = 0; u < 16; u++) {
        int c = tid + u * 256;
        int r = c >> 5, ch = c & 31;
        cp_async16(qtmp + r * 512 + ((ch ^ (r & 7)) << 4), qsrc + (size_t)r * 256 + ch * 8);
    }
    CP_COMMIT();
    attn_load_kv(sb, ksrc0, vsrc0, 0, tid);
    CP_COMMIT();
    CP_WAIT1();               // Q done (kv0 may still be in flight)
    __syncthreads();

    // extract Q fragments -> registers (8 k-steps x (hi4 + lo4))
    const int a_row = wid * 16 + (lane & 15);
    const uint32_t a_off = a_row * 512;
    const int a_x = a_row & 7;
    const int a_k16 = lane >> 4;
    uint32_t qh[8][4], ql[8][4];
#pragma unroll
    for (int kst = 0; kst < 8; kst++) {
        ldmx4(qh[kst][0], qh[kst][1], qh[kst][2], qh[kst][3],
              qtmp + a_off + (((kst * 2 + a_k16) ^ a_x) << 4));
        ldmx4(ql[kst][0], ql[kst][1], ql[kst][2], ql[kst][3],
              qtmp + a_off + (((16 + kst * 2 + a_k16) ^ a_x) << 4));
    }
    __syncthreads();          // Q smem free; stage 2 now usable for KV

    if (ntiles > 1) {
        attn_load_kv(sb + KV_ST, ksrc0, vsrc0, 1, tid);
        CP_COMMIT();
    }

    const int b_row = (lane & 7) + ((lane >> 4) << 3);
    const int b_k16 = (lane >> 3) & 1;

    uint32_t kb_off[4]; int kb_x[4];
#pragma unroll
    for (int np = 0; np < 4; np++) {
        int row = np * 16 + b_row;
        kb_off[np] = row * 512; kb_x[np] = row & 7;
    }
    uint32_t vb_off[8]; int vb_x[8];
#pragma unroll
    for (int np = 0; np < 8; np++) {
        int row = np * 16 + b_row;
        vb_off[np] = row * 128; vb_x[np] = row & 7;
    }

    float o[16][4];
#pragma unroll
    for (int nt = 0; nt < 16; nt++)
#pragma unroll
        for (int c = 0; c < 4; c++) o[nt][c] = 0.f;
    float mA = -1e30f, mB = -1e30f, lA = 0.f, lB = 0.f;

    int stg = 0;
    for (int kt = 0; kt < ntiles; kt++) {
        if (kt + 2 < ntiles) {
            int ps = stg + 2; if (ps >= 3) ps -= 3;
            attn_load_kv(sb + ps * KV_ST, ksrc0, vsrc0, kt + 2, tid);
            CP_COMMIT();
        }
        const int na = ntiles - 1 - kt;
        if (na >= 2)      { CP_WAIT2(); }
        else if (na == 1) { CP_WAIT1(); }
        else              { CP_WAIT0(); }
        __syncthreads();
        const uint32_t ksm = sb + stg * KV_ST;
        const uint32_t vsm = ksm + K_SM_BYTES;

        // ---- QK^T: 3-term split, Q from registers ----
        float s[8][4];
#pragma unroll
        for (int nt = 0; nt < 8; nt++)
#pragma unroll
            for (int c = 0; c < 4; c++) s[nt][c] = 0.f;

#pragma unroll
        for (int kst = 0; kst < 8; kst++) {
#pragma unroll
            for (int np = 0; np < 4; np++) {
                uint32_t bh[4], bl[4];
                ldmx4(bh[0], bh[1], bh[2], bh[3],
                      ksm + kb_off[np] + (((kst * 2 + b_k16) ^ kb_x[np]) << 4));
                ldmx4(bl[0], bl[1], bl[2], bl[3],
                      ksm + kb_off[np] + (((16 + kst * 2 + b_k16) ^ kb_x[np]) << 4));
                mma_bf16(s[2*np],   qh[kst], bh[0], bh[1]);
                mma_bf16(s[2*np+1], qh[kst], bh[2], bh[3]);
                mma_bf16(s[2*np],   qh[kst], bl[0], bl[1]);
                mma_bf16(s[2*np+1], qh[kst], bl[2], bl[3]);
                mma_bf16(s[2*np],   ql[kst], bh[0], bh[1]);
                mma_bf16(s[2*np+1], ql[kst], bh[2], bh[3]);
            }
        }

        if (kt * 64 + 64 > seqlen) {
            const int kbase = kt * 64 + (lane & 3) * 2;
#pragma unroll
            for (int nt = 0; nt < 8; nt++)
#pragma unroll
                for (int c = 0; c < 4; c++) {
                    int gk = kbase + nt * 8 + (c & 1);
                    if (gk >= seqlen) s[nt][c] = -1e30f;
                }
        }

        // ---- online softmax ----
        float pmA = -1e30f, pmB = -1e30f;
#pragma unroll
        for (int nt = 0; nt < 8; nt++) {
            pmA = fmaxf(pmA, fmaxf(s[nt][0], s[nt][1]));
            pmB = fmaxf(pmB, fmaxf(s[nt][2], s[nt][3]));
        }
        pmA = fmaxf(pmA, __shfl_xor_sync(0xffffffffu, pmA, 1));
        pmA = fmaxf(pmA, __shfl_xor_sync(0xffffffffu, pmA, 2));
        pmB = fmaxf(pmB, __shfl_xor_sync(0xffffffffu, pmB, 1));
        pmB = fmaxf(pmB, __shfl_xor_sync(0xffffffffu, pmB, 2));

        const float mnA = fmaxf(mA, pmA), mnB = fmaxf(mB, pmB);
        const float fA = __expf(mA - mnA), fB = __expf(mB - mnB);
        float sumA = 0.f, sumB = 0.f;
#pragma unroll
        for (int nt = 0; nt < 8; nt++) {
            s[nt][0] = __expf(s[nt][0] - mnA); sumA += s[nt][0];
            s[nt][1] = __expf(s[nt][1] - mnA); sumA += s[nt][1];
            s[nt][2] = __expf(s[nt][2] - mnB); sumB += s[nt][2];
            s[nt][3] = __expf(s[nt][3] - mnB); sumB += s[nt][3];
        }
        sumA += __shfl_xor_sync(0xffffffffu, sumA, 1);
        sumA += __shfl_xor_sync(0xffffffffu, sumA, 2);
        sumB += __shfl_xor_sync(0xffffffffu, sumB, 1);
        sumB += __shfl_xor_sync(0xffffffffu, sumB, 2);

        mA = mnA; mB = mnB;
        lA = lA * fA + sumA;
        lB = lB * fB + sumB;

#pragma unroll
        for (int nt = 0; nt < 16; nt++) {
            o[nt][0] *= fA; o[nt][1] *= fA;
            o[nt][2] *= fB; o[nt][3] *= fB;
        }

        // ---- P.V: 3-term split, kk-outer (only 8 split regs live) ----
#pragma unroll
        for (int kk = 0; kk < 4; kk++) {
            uint32_t ph[4], pl[4];
            split2(s[2*kk][0],   s[2*kk][1],   ph[0], pl[0]);
            split2(s[2*kk][2],   s[2*kk][3],   ph[1], pl[1]);
            split2(s[2*kk+1][0], s[2*kk+1][1], ph[2], pl[2]);
            split2(s[2*kk+1][2], s[2*kk+1][3], ph[3], pl[3]);
#pragma unroll
            for (int np = 0; np < 8; np++) {
                uint32_t bvh[4], bvl[4];
                ldmx4(bvh[0], bvh[1], bvh[2], bvh[3],
                      vsm + vb_off[np] + (((kk * 2 + b_k16) ^ vb_x[np]) << 4));
                ldmx4(bvl[0], bvl[1], bvl[2], bvl[3],
                      vsm + 128 * 128 + vb_off[np] + (((kk * 2 + b_k16) ^ vb_x[np]) << 4));
                mma_bf16(o[2*np],   ph, bvh[0], bvh[1]);
                mma_bf16(o[2*np+1], ph, bvh[2], bvh[3]);
                mma_bf16(o[2*np],   ph, bvl[0], bvl[1]);
                mma_bf16(o[2*np+1], ph, bvl[2], bvl[3]);
                mma_bf16(o[2*np],   pl, bvh[0], bvh[1]);
                mma_bf16(o[2*np+1], pl, bvh[2], bvh[3]);
            }
        }
        __syncthreads();
        stg = (stg + 1 == 3) ? 0 : stg + 1;
    }

    // epilogue: write hi/hi/lo split directly into ao3 [S][K3]
    const float iA = 1.f / lA, iB = 1.f / lB;
    const int row0 = qb * 128 + wid * 16 + (lane >> 2);
    const int col0 = h * 128 + (lane & 3) * 2;
#pragma unroll
    for (int nt = 0; nt < 16; nt++) {
        float xA = o[nt][0] * iA, yA = o[nt][1] * iA;
        float xB = o[nt][2] * iB, yB = o[nt][3] * iB;
        uint32_t hA, loA, hB, loB;
        split2(xA, yA, hA, loA);
        split2(xB, yB, hB, loB);
        __nv_bfloat16* pA = ao3 + (size_t)row0 * K3 + col0 + nt * 8;
        __nv_bfloat16* pB = ao3 + (size_t)(row0 + 8) * K3 + col0 + nt * 8;
        *(uint32_t*)&pA[0]        = hA;
        *(uint32_t*)&pA[DIM]      = hA;
        *(uint32_t*)&pA[2 * DIM]  = loA;
        *(uint32_t*)&pB[0]        = hB;
        *(uint32_t*)&pB[DIM]      = hB;
        *(uint32_t*)&pB[2 * DIM]  = loB;
    }
}

// ---------------- launch ----------------------------------------------------
extern "C" void kernel_launch(void* const* d_in, const int* in_sizes, int n_in,
                              void* d_out, int out_size)
{
    const float* x    = (const float*)d_in[0];
    const float* Wq   = (const float*)d_in[1];
    const float* bq   = (const float*)d_in[2];
    const float* Wk   = (const float*)d_in[3];
    const float* bk   = (const float*)d_in[4];
    const float* Wv   = (const float*)d_in[5];
    const float* bv   = (const float*)d_in[6];
    const float* Wo   = (const float*)d_in[7];
    const float* bo   = (const float*)d_in[8];
    const float* nqw  = (const float*)d_in[9];
    const float* nkw  = (const float*)d_in[10];
    const float* cosb = (const float*)d_in[11];
    const float* sinb = (const float*)d_in[12];
    const int*   seql = (const int*)d_in[13];
    float* out = (float*)d_out;

    float *qkv, *bias3;
    __nv_bfloat16 *x3, *ao3, *w3, *qsb, *ksb, *vtb;
    cudaGetSymbolAddress((void**)&qkv,   g_qkv);
    cudaGetSymbolAddress((void**)&bias3, g_bias3);
    cudaGetSymbolAddress((void**)&x3,    g_x3);
    cudaGetSymbolAddress((void**)&ao3,   g_ao3);
    cudaGetSymbolAddress((void**)&w3,    g_w3);
    cudaGetSymbolAddress((void**)&qsb,   g_qs);
    cudaGetSymbolAddress((void**)&ksb,   g_ks);
    cudaGetSymbolAddress((void**)&vtb,   g_vt);

    cudaFuncSetAttribute(gemm_mma_kernel, cudaFuncAttributeMaxDynamicSharedMemorySize, SMEM_G);
    cudaFuncSetAttribute(attn_mma_kernel, cudaFuncAttributeMaxDynamicSharedMemorySize, ATTN_SMEM);

    const int nxp = S_LEN * DIM / 2, nwp = DIM * DIM / 2;
    cvt3v_kernel<<<(nxp + 255) / 256, 256>>>(x,  x3, nxp, 0);
    cvt3v_kernel<<<(nwp + 255) / 256, 256>>>(Wq, w3 + 0 * (size_t)DIM * K3, nwp, 1);
    cvt3v_kernel<<<(nwp + 255) / 256, 256>>>(Wk, w3 + 1 * (size_t)DIM * K3, nwp, 1);
    cvt3v_kernel<<<(nwp + 255) / 256, 256>>>(Wv, w3 + 2 * (size_t)DIM * K3, nwp, 1);
    cvt3v_kernel<<<(nwp + 255) / 256, 256>>>(Wo, w3 + 3 * (size_t)DIM * K3, nwp, 1);
    bias3_kernel<<<(3 * DIM + 255) / 256, 256>>>(bq, bk, bv, bias3);

    gemm_mma_kernel<<<dim3(3 * DIM / GBN, S_LEN / GBM), 256, SMEM_G>>>(
        x3, w3, bias3, qkv, 3 * DIM);

    const float qscale = 0.08838834764831845f;   // 1/sqrt(128)
    rms_rope_split_kernel<<<S_LEN, 256>>>(qkv,        nqw, cosb, sinb, qsb, qscale);
    rms_rope_split_kernel<<<S_LEN, 256>>>(qkv + DIM,  nkw, cosb, sinb, ksb, 1.0f);
    vsplit_t_kernel<<<dim3(S_LEN / 32, DIM / 32), 256>>>(qkv, vtb);

    attn_mma_kernel<<<dim3(S_LEN / 128, NH), 256, ATTN_SMEM>>>(qsb, ksb, vtb, ao3, seql);

    gemm_mma_kernel<<<dim3(DIM / GBN, S_LEN / GBM), 256, SMEM_G>>>(
        ao3, w3 + 3 * (size_t)DIM * K3, bo, out, DIM);
}